// round 1
// baseline (speedup 1.0000x reference)
#include <cuda_runtime.h>
#include <math.h>

#define B_  4
#define S_  2048
#define D_  1024
#define H_  16
#define HD_ 64
#define M_  (B_*S_)   // 8192

// Scratch (static device globals; no allocations allowed)
__device__ float g_q[B_*S_*D_];
__device__ float g_k[B_*S_*D_];
__device__ float g_v[B_*S_*D_];
__device__ float g_y[B_*S_*D_];

// ---------------------------------------------------------------------------
// GEMM: Y = relu(X @ W^T + bias). X:[M,K] row-major, W:[N,K] row-major.
// HEADSPLIT=1 writes Y into [B,H,S,HD] layout; else plain [M,N].
// Tile: 64x64, BK=16, 256 threads, 4x4 per-thread micro-tile.
// ---------------------------------------------------------------------------
template<int HEADSPLIT>
__global__ __launch_bounds__(256)
void proj_kernel(const float* __restrict__ X, const float* __restrict__ W,
                 const float* __restrict__ bias, float* __restrict__ Y) {
    const int K = 1024;
    const int N = 1024;
    __shared__ float Xs[16][64];
    __shared__ float Ws[16][64];

    const int tid = threadIdx.x;
    const int tx  = tid & 15;        // 0..15 -> N micro
    const int ty  = tid >> 4;        // 0..15 -> M micro
    const int m0  = blockIdx.y * 64;
    const int n0  = blockIdx.x * 64;

    const int lrow = tid >> 2;       // 0..63 (tile row for loads)
    const int lk   = (tid & 3) * 4;  // 0,4,8,12 (k offset for loads)

    const float* Xp = X + (size_t)(m0 + lrow) * K + lk;
    const float* Wp = W + (size_t)(n0 + lrow) * K + lk;

    float acc[4][4];
#pragma unroll
    for (int i = 0; i < 4; i++)
#pragma unroll
        for (int j = 0; j < 4; j++) acc[i][j] = 0.f;

    for (int k0 = 0; k0 < K; k0 += 16) {
        float4 xv = *(const float4*)(Xp + k0);
        float4 wv = *(const float4*)(Wp + k0);
        Xs[lk+0][lrow] = xv.x; Xs[lk+1][lrow] = xv.y;
        Xs[lk+2][lrow] = xv.z; Xs[lk+3][lrow] = xv.w;
        Ws[lk+0][lrow] = wv.x; Ws[lk+1][lrow] = wv.y;
        Ws[lk+2][lrow] = wv.z; Ws[lk+3][lrow] = wv.w;
        __syncthreads();

#pragma unroll
        for (int kk = 0; kk < 16; ++kk) {
            float a[4], b[4];
#pragma unroll
            for (int i = 0; i < 4; i++) a[i] = Xs[kk][ty*4 + i];
#pragma unroll
            for (int j = 0; j < 4; j++) b[j] = Ws[kk][tx*4 + j];
#pragma unroll
            for (int i = 0; i < 4; i++)
#pragma unroll
                for (int j = 0; j < 4; j++) acc[i][j] += a[i] * b[j];
        }
        __syncthreads();
    }

#pragma unroll
    for (int i = 0; i < 4; i++) {
        const int m = m0 + ty*4 + i;
#pragma unroll
        for (int j = 0; j < 4; j++) {
            const int n = n0 + tx*4 + j;
            float v = acc[i][j] + bias[n];
            v = fmaxf(v, 0.f);
            if (HEADSPLIT) {
                const int b  = m / S_;
                const int s  = m % S_;
                const int h  = n / HD_;
                const int hd = n % HD_;
                Y[(((size_t)(b*H_ + h))*S_ + s)*HD_ + hd] = v;
            } else {
                Y[(size_t)m * N + n] = v;
            }
        }
    }
}

// ---------------------------------------------------------------------------
// Flash attention (fp32, non-causal). Q,K,V in [BH, S, HD] layout.
// Block: 64 q-rows x full HD. Iterates K/V in 64-row tiles, online softmax.
// Output written merged-heads into [B, S, D].
// ---------------------------------------------------------------------------
#define ATT_SMEM ((4*64*64 + 64*16 + 64 + 64) * sizeof(float))

__global__ __launch_bounds__(256)
void attn_kernel(const float* __restrict__ Q, const float* __restrict__ K,
                 const float* __restrict__ V, float* __restrict__ Y) {
    extern __shared__ float sm[];
    float* Qs   = sm;                 // [64][64]
    float* Ks   = Qs  + 64*64;        // [64][64]
    float* Vs   = Ks  + 64*64;        // [64][64]
    float* Ps   = Vs  + 64*64;        // [64][64]
    float* red  = Ps  + 64*64;        // [64][16]
    float* mrow = red + 64*16;        // [64]
    float* lrow = mrow + 64;          // [64]

    const int bh  = blockIdx.y;        // 0..63
    const int q0  = blockIdx.x * 64;
    const int tid = threadIdx.x;
    const int tx  = tid & 15;
    const int ty  = tid >> 4;

    const size_t base = (size_t)bh * S_ * HD_;
    const float* Qp = Q + base;
    const float* Kp = K + base;
    const float* Vp = V + base;

    const int lrw = tid >> 2;          // 0..63
    const int lc  = (tid & 3) * 16;    // 0,16,32,48
    const float scale = 0.125f;        // 1/sqrt(64)

    // Load Q tile (pre-scaled)
#pragma unroll
    for (int c = 0; c < 16; c += 4) {
        float4 v = *(const float4*)(Qp + (size_t)(q0 + lrw) * HD_ + lc + c);
        v.x *= scale; v.y *= scale; v.z *= scale; v.w *= scale;
        *(float4*)&Qs[lrw*64 + lc + c] = v;
    }
    if (tid < 64) { mrow[tid] = -INFINITY; lrow[tid] = 0.f; }

    float o[4][4];
#pragma unroll
    for (int i = 0; i < 4; i++)
#pragma unroll
        for (int j = 0; j < 4; j++) o[i][j] = 0.f;

    for (int kt = 0; kt < S_ / 64; ++kt) {
        __syncthreads();   // previous iteration done with Ks/Vs/Ps/red
        const int k0 = kt * 64;
#pragma unroll
        for (int c = 0; c < 16; c += 4) {
            *(float4*)&Ks[lrw*64 + lc + c] =
                *(const float4*)(Kp + (size_t)(k0 + lrw) * HD_ + lc + c);
            *(float4*)&Vs[lrw*64 + lc + c] =
                *(const float4*)(Vp + (size_t)(k0 + lrw) * HD_ + lc + c);
        }
        __syncthreads();

        // S = Q @ K^T  (scale already folded into Q)
        float acc[4][4];
#pragma unroll
        for (int i = 0; i < 4; i++)
#pragma unroll
            for (int j = 0; j < 4; j++) acc[i][j] = 0.f;

#pragma unroll
        for (int d = 0; d < 64; d += 4) {
            float4 qa[4], kb[4];
#pragma unroll
            for (int i = 0; i < 4; i++) qa[i] = *(const float4*)&Qs[(ty*4+i)*64 + d];
#pragma unroll
            for (int j = 0; j < 4; j++) kb[j] = *(const float4*)&Ks[(tx*4+j)*64 + d];
#pragma unroll
            for (int i = 0; i < 4; i++)
#pragma unroll
                for (int j = 0; j < 4; j++) {
                    acc[i][j] += qa[i].x*kb[j].x + qa[i].y*kb[j].y
                               + qa[i].z*kb[j].z + qa[i].w*kb[j].w;
                }
        }

        // partial row max
#pragma unroll
        for (int i = 0; i < 4; i++) {
            float pm = acc[i][0];
#pragma unroll
            for (int j = 1; j < 4; j++) pm = fmaxf(pm, acc[i][j]);
            red[(ty*4+i)*16 + tx] = pm;
        }
        __syncthreads();

        float newm[4], alpha[4], psum[4];
#pragma unroll
        for (int i = 0; i < 4; i++) {
            const int r = ty*4 + i;
            float mx = red[r*16];
#pragma unroll
            for (int t = 1; t < 16; t++) mx = fmaxf(mx, red[r*16 + t]);
            const float mo = mrow[r];
            const float nm = fmaxf(mo, mx);
            newm[i]  = nm;
            alpha[i] = __expf(mo - nm);
            float s = 0.f;
#pragma unroll
            for (int j = 0; j < 4; j++) {
                float p = __expf(acc[i][j] - nm);
                Ps[r*64 + tx*4 + j] = p;
                s += p;
            }
            psum[i] = s;
#pragma unroll
            for (int j = 0; j < 4; j++) o[i][j] *= alpha[i];
        }
        __syncthreads();   // all max reads done before red reuse

#pragma unroll
        for (int i = 0; i < 4; i++) red[(ty*4+i)*16 + tx] = psum[i];
        __syncthreads();   // psums + Ps visible

        if (tx == 0) {
#pragma unroll
            for (int i = 0; i < 4; i++) {
                const int r = ty*4 + i;
                float s = 0.f;
#pragma unroll
                for (int t = 0; t < 16; t++) s += red[r*16 + t];
                lrow[r] = lrow[r] * alpha[i] + s;
                mrow[r] = newm[i];
            }
        }

        // O += P @ V
#pragma unroll 4
        for (int kk = 0; kk < 64; ++kk) {
            float a[4];
#pragma unroll
            for (int i = 0; i < 4; i++) a[i] = Ps[(ty*4+i)*64 + kk];
            float4 bv = *(const float4*)&Vs[kk*64 + tx*4];
#pragma unroll
            for (int i = 0; i < 4; i++) {
                o[i][0] += a[i]*bv.x; o[i][1] += a[i]*bv.y;
                o[i][2] += a[i]*bv.z; o[i][3] += a[i]*bv.w;
            }
        }
    }
    __syncthreads();   // lrow final

    const int b = bh / H_;
    const int h = bh % H_;
#pragma unroll
    for (int i = 0; i < 4; i++) {
        const int q   = q0 + ty*4 + i;
        const float inv = 1.f / lrow[ty*4 + i];
        float* yp = Y + ((size_t)(b*S_ + q)) * D_ + h*HD_ + tx*4;
        float4 v;
        v.x = o[i][0]*inv; v.y = o[i][1]*inv; v.z = o[i][2]*inv; v.w = o[i][3]*inv;
        *(float4*)yp = v;
    }
}

// ---------------------------------------------------------------------------
extern "C" void kernel_launch(void* const* d_in, const int* in_sizes, int n_in,
                              void* d_out, int out_size) {
    (void)in_sizes; (void)n_in; (void)out_size;
    const float* q  = (const float*)d_in[0];
    const float* k  = (const float*)d_in[1];
    const float* v  = (const float*)d_in[2];
    const float* Wq = (const float*)d_in[3];
    const float* bq = (const float*)d_in[4];
    const float* Wk = (const float*)d_in[5];
    const float* bk = (const float*)d_in[6];
    const float* Wv = (const float*)d_in[7];
    const float* bv = (const float*)d_in[8];
    const float* Wo = (const float*)d_in[9];
    const float* bo = (const float*)d_in[10];
    float* out = (float*)d_out;

    float *gq, *gk, *gv, *gy;
    cudaGetSymbolAddress((void**)&gq, g_q);
    cudaGetSymbolAddress((void**)&gk, g_k);
    cudaGetSymbolAddress((void**)&gv, g_v);
    cudaGetSymbolAddress((void**)&gy, g_y);

    cudaFuncSetAttribute(attn_kernel,
                         cudaFuncAttributeMaxDynamicSharedMemorySize, (int)ATT_SMEM);

    dim3 gThreads(256);
    dim3 gGrid(1024/64, M_/64);   // (16, 128)

    proj_kernel<1><<<gGrid, gThreads>>>(q, Wq, bq, gq);
    proj_kernel<1><<<gGrid, gThreads>>>(k, Wk, bk, gk);
    proj_kernel<1><<<gGrid, gThreads>>>(v, Wv, bv, gv);

    dim3 aGrid(S_/64, B_*H_);     // (32, 64)
    attn_kernel<<<aGrid, gThreads, ATT_SMEM>>>(gq, gk, gv, gy);

    proj_kernel<0><<<gGrid, gThreads>>>(gy, Wo, bo, out);
}

// round 2
// speedup vs baseline: 7.2655x; 7.2655x over previous
#include <cuda_runtime.h>
#include <cuda_bf16.h>
#include <math.h>

#define B_  4
#define S_  2048
#define D_  1024
#define H_  16
#define HD_ 64
#define M_  (B_*S_)   // 8192

// log2(e) * (1/sqrt(64)) folded into Q projection epilogue
#define QSCALE 0.18033688011112042f

// Scratch (static device globals; no allocations allowed)
__device__ __nv_bfloat16 g_qb[B_*S_*D_];   // [bh][s][hd]
__device__ __nv_bfloat16 g_kb[B_*S_*D_];   // [bh][s][hd]
__device__ __nv_bfloat16 g_vb[B_*S_*D_];   // [bh][hd][s]  (transposed!)
__device__ float         g_y [B_*S_*D_];   // [b][s][d]

// ---------------------------------------------------------------------------
// helpers
// ---------------------------------------------------------------------------
__device__ __forceinline__ unsigned f2tf(float x) {
    unsigned r; asm("cvt.rna.tf32.f32 %0, %1;" : "=r"(r) : "f"(x)); return r;
}
__device__ __forceinline__ float ex2f(float x) {
    float r; asm("ex2.approx.f32 %0, %1;" : "=f"(r) : "f"(x)); return r;
}
__device__ __forceinline__ void mma_tf32(float* c, const unsigned* a, const unsigned* b) {
    asm volatile("mma.sync.aligned.m16n8k8.row.col.f32.tf32.tf32.f32 "
        "{%0,%1,%2,%3},{%4,%5,%6,%7},{%8,%9},{%0,%1,%2,%3};"
        : "+f"(c[0]), "+f"(c[1]), "+f"(c[2]), "+f"(c[3])
        : "r"(a[0]), "r"(a[1]), "r"(a[2]), "r"(a[3]), "r"(b[0]), "r"(b[1]));
}
__device__ __forceinline__ void mma_bf16(float* c, const unsigned* a, const unsigned* b) {
    asm volatile("mma.sync.aligned.m16n8k16.row.col.f32.bf16.bf16.f32 "
        "{%0,%1,%2,%3},{%4,%5,%6,%7},{%8,%9},{%0,%1,%2,%3};"
        : "+f"(c[0]), "+f"(c[1]), "+f"(c[2]), "+f"(c[3])
        : "r"(a[0]), "r"(a[1]), "r"(a[2]), "r"(a[3]), "r"(b[0]), "r"(b[1]));
}
__device__ __forceinline__ unsigned packbf(float lo, float hi) {
    __nv_bfloat162 h = __floats2bfloat162_rn(lo, hi);
    return *reinterpret_cast<unsigned*>(&h);
}

// ---------------------------------------------------------------------------
// tf32 tensor-core GEMM: out = relu(X @ W^T + bias) * scale
// X:[Mrows,1024] rm, W:[Ncols,1024] rm.
// MODE 0: fp32 out [Mrows,1024]                 (bias on col)
// MODE 1: bf16 headsplit out [B,H,S,HD]         (bias on col)
// MODE 2: bf16 out [*, row-feature, col-token] -> [B,H,HD,S] (bias on ROW)
// Tile 128x128, BK=32, 256 threads (8 warps: 2 m x 4 n), reg-prefetch pipeline.
// ---------------------------------------------------------------------------
template<int MODE>
__global__ __launch_bounds__(256)
void proj_tc(const float* __restrict__ X, const float* __restrict__ W,
             const float* __restrict__ bias, void* __restrict__ Yv,
             float scale)
{
    const int K = 1024;
    __shared__ unsigned As[128 * 36];
    __shared__ unsigned Bs[128 * 36];

    const int tid  = threadIdx.x;
    const int lane = tid & 31, wid = tid >> 5;
    const int g    = lane >> 2, qq = lane & 3;
    const int wm   = (wid & 1) * 64;
    const int wn   = (wid >> 1) * 32;
    const int m0   = blockIdx.y * 128, n0 = blockIdx.x * 128;

    const int lrow = tid >> 1;
    const int lcol = (tid & 1) * 16;
    const float* Xp = X + (size_t)(m0 + lrow) * K + lcol;
    const float* Wp = W + (size_t)(n0 + lrow) * K + lcol;

    float acc[4][4][4];
#pragma unroll
    for (int mt = 0; mt < 4; mt++)
#pragma unroll
        for (int nt = 0; nt < 4; nt++)
#pragma unroll
            for (int j = 0; j < 4; j++) acc[mt][nt][j] = 0.f;

    float4 xv[4], wv[4];
#pragma unroll
    for (int j = 0; j < 4; j++) { xv[j] = *(const float4*)(Xp + j*4); wv[j] = *(const float4*)(Wp + j*4); }

    for (int k0 = 0; k0 < K; k0 += 32) {
        __syncthreads();
#pragma unroll
        for (int j = 0; j < 4; j++) {
            uint4 u;
            u.x = f2tf(xv[j].x); u.y = f2tf(xv[j].y); u.z = f2tf(xv[j].z); u.w = f2tf(xv[j].w);
            *(uint4*)&As[lrow*36 + lcol + j*4] = u;
            u.x = f2tf(wv[j].x); u.y = f2tf(wv[j].y); u.z = f2tf(wv[j].z); u.w = f2tf(wv[j].w);
            *(uint4*)&Bs[lrow*36 + lcol + j*4] = u;
        }
        __syncthreads();

        if (k0 + 32 < K) {
#pragma unroll
            for (int j = 0; j < 4; j++) {
                xv[j] = *(const float4*)(Xp + k0 + 32 + j*4);
                wv[j] = *(const float4*)(Wp + k0 + 32 + j*4);
            }
        }

#pragma unroll
        for (int ks = 0; ks < 4; ks++) {
            const int kb = ks * 8;
            unsigned a[4][4], b[4][2];
#pragma unroll
            for (int mt = 0; mt < 4; mt++) {
                const int r = wm + mt*16 + g;
                a[mt][0] = As[r*36 + kb + qq];
                a[mt][1] = As[(r+8)*36 + kb + qq];
                a[mt][2] = As[r*36 + kb + qq + 4];
                a[mt][3] = As[(r+8)*36 + kb + qq + 4];
            }
#pragma unroll
            for (int nt = 0; nt < 4; nt++) {
                const int r = wn + nt*8 + g;
                b[nt][0] = Bs[r*36 + kb + qq];
                b[nt][1] = Bs[r*36 + kb + qq + 4];
            }
#pragma unroll
            for (int mt = 0; mt < 4; mt++)
#pragma unroll
                for (int nt = 0; nt < 4; nt++) mma_tf32(acc[mt][nt], a[mt], b[nt]);
        }
    }

    // epilogue
#pragma unroll
    for (int mt = 0; mt < 4; mt++) {
        const int r0 = m0 + wm + mt*16 + g;
        const int r1 = r0 + 8;
#pragma unroll
        for (int nt = 0; nt < 4; nt++) {
            const int c0 = n0 + wn + nt*8 + qq*2;
            float v00, v01, v10, v11;
            if (MODE == 2) {
                const float bb0 = bias[r0], bb1 = bias[r1];
                v00 = fmaxf(acc[mt][nt][0] + bb0, 0.f) * scale;
                v01 = fmaxf(acc[mt][nt][1] + bb0, 0.f) * scale;
                v10 = fmaxf(acc[mt][nt][2] + bb1, 0.f) * scale;
                v11 = fmaxf(acc[mt][nt][3] + bb1, 0.f) * scale;
            } else {
                const float bb0 = bias[c0], bb1 = bias[c0 + 1];
                v00 = fmaxf(acc[mt][nt][0] + bb0, 0.f) * scale;
                v01 = fmaxf(acc[mt][nt][1] + bb1, 0.f) * scale;
                v10 = fmaxf(acc[mt][nt][2] + bb0, 0.f) * scale;
                v11 = fmaxf(acc[mt][nt][3] + bb1, 0.f) * scale;
            }
            if (MODE == 0) {
                float* Y = (float*)Yv;
                float2 p0 = {v00, v01}, p1 = {v10, v11};
                *(float2*)&Y[(size_t)r0*1024 + c0] = p0;
                *(float2*)&Y[(size_t)r1*1024 + c0] = p1;
            } else if (MODE == 1) {
                __nv_bfloat16* Y = (__nv_bfloat16*)Yv;
                const int h = c0 >> 6, hd = c0 & 63;
                {
                    const int b = r0 >> 11, s = r0 & 2047;
                    __nv_bfloat162 hh = __floats2bfloat162_rn(v00, v01);
                    *(__nv_bfloat162*)&Y[(((size_t)(b*H_ + h))*S_ + s)*HD_ + hd] = hh;
                }
                {
                    const int b = r1 >> 11, s = r1 & 2047;
                    __nv_bfloat162 hh = __floats2bfloat162_rn(v10, v11);
                    *(__nv_bfloat162*)&Y[(((size_t)(b*H_ + h))*S_ + s)*HD_ + hd] = hh;
                }
            } else {
                // MODE 2: rows = (h,hd) features, cols = (b,s) tokens
                __nv_bfloat16* Y = (__nv_bfloat16*)Yv;
                const int bcol = c0 >> 11, s = c0 & 2047;
                {
                    const int h = r0 >> 6, hd = r0 & 63;
                    __nv_bfloat162 hh = __floats2bfloat162_rn(v00, v01);
                    *(__nv_bfloat162*)&Y[(((size_t)(bcol*H_ + h))*HD_ + hd)*S_ + s] = hh;
                }
                {
                    const int h = r1 >> 6, hd = r1 & 63;
                    __nv_bfloat162 hh = __floats2bfloat162_rn(v10, v11);
                    *(__nv_bfloat162*)&Y[(((size_t)(bcol*H_ + h))*HD_ + hd)*S_ + s] = hh;
                }
            }
        }
    }
}

// ---------------------------------------------------------------------------
// bf16 tensor-core flash attention (log2-domain softmax; Q pre-scaled).
// Q,K: [bh][s][hd] bf16.  V: [bh][hd][s] bf16 (transposed).  Y: [b][s][D] f32.
// Block: 64 q-rows, 128 threads (4 warps x 16 rows). KV tiles of 64.
// P stays in registers (C-frag == A-frag layout for m16n8k16).
// ---------------------------------------------------------------------------
__global__ __launch_bounds__(128)
void attn_tc(const __nv_bfloat16* __restrict__ Q,
             const __nv_bfloat16* __restrict__ K,
             const __nv_bfloat16* __restrict__ V,
             float* __restrict__ Y)
{
    __shared__ unsigned Qs[64 * 36];
    __shared__ unsigned Ks[64 * 36];
    __shared__ unsigned Vs[64 * 36];

    const int tid  = threadIdx.x;
    const int lane = tid & 31, wid = tid >> 5;
    const int g    = lane >> 2, qq = lane & 3;
    const int bh   = blockIdx.y;
    const int q0   = blockIdx.x * 64;
    const size_t base = (size_t)bh * S_ * HD_;

    // stage Q tile (bf16, already scaled by QSCALE in projection)
    {
        const int r = tid >> 1, c = (tid & 1) * 16;  // c in uints
        const uint4* src = (const uint4*)(Q + base + (size_t)(q0 + r)*HD_ + c*2);
#pragma unroll
        for (int j = 0; j < 4; j++) *(uint4*)&Qs[r*36 + c + j*4] = src[j];
    }
    __syncthreads();

    unsigned qa[4][4];
#pragma unroll
    for (int c = 0; c < 4; c++) {
        const int rr = wid*16 + g;
        qa[c][0] = Qs[rr*36 + c*8 + qq];
        qa[c][1] = Qs[(rr+8)*36 + c*8 + qq];
        qa[c][2] = Qs[rr*36 + c*8 + qq + 4];
        qa[c][3] = Qs[(rr+8)*36 + c*8 + qq + 4];
    }

    float m0r = -1e30f, m1r = -1e30f, l0 = 0.f, l1 = 0.f;
    float o[8][4];
#pragma unroll
    for (int nt = 0; nt < 8; nt++)
#pragma unroll
        for (int j = 0; j < 4; j++) o[nt][j] = 0.f;

    for (int kt = 0; kt < S_/64; kt++) {
        __syncthreads();
        {
            const int r = tid >> 1, c = (tid & 1) * 16;
            const uint4* ks = (const uint4*)(K + base + (size_t)(kt*64 + r)*HD_ + c*2);
            const uint4* vs = (const uint4*)(V + base + (size_t)r*S_ + kt*64 + c*2);
#pragma unroll
            for (int j = 0; j < 4; j++) {
                *(uint4*)&Ks[r*36 + c + j*4] = ks[j];
                *(uint4*)&Vs[r*36 + c + j*4] = vs[j];
            }
        }
        __syncthreads();

        // S = Q @ K^T  (log2-domain scores)
        float s[8][4];
#pragma unroll
        for (int nt = 0; nt < 8; nt++)
#pragma unroll
            for (int j = 0; j < 4; j++) s[nt][j] = 0.f;
#pragma unroll
        for (int c = 0; c < 4; c++) {
#pragma unroll
            for (int nt = 0; nt < 8; nt++) {
                unsigned b[2];
                b[0] = Ks[(nt*8+g)*36 + c*8 + qq];
                b[1] = Ks[(nt*8+g)*36 + c*8 + qq + 4];
                mma_bf16(s[nt], qa[c], b);
            }
        }

        // online softmax (base-2)
        float mx0 = s[0][0], mx1 = s[0][2];
#pragma unroll
        for (int nt = 0; nt < 8; nt++) {
            mx0 = fmaxf(mx0, fmaxf(s[nt][0], s[nt][1]));
            mx1 = fmaxf(mx1, fmaxf(s[nt][2], s[nt][3]));
        }
        mx0 = fmaxf(mx0, __shfl_xor_sync(0xffffffffu, mx0, 1));
        mx0 = fmaxf(mx0, __shfl_xor_sync(0xffffffffu, mx0, 2));
        mx1 = fmaxf(mx1, __shfl_xor_sync(0xffffffffu, mx1, 1));
        mx1 = fmaxf(mx1, __shfl_xor_sync(0xffffffffu, mx1, 2));

        const float nm0 = fmaxf(m0r, mx0), nm1 = fmaxf(m1r, mx1);
        const float a0 = ex2f(m0r - nm0), a1 = ex2f(m1r - nm1);
        m0r = nm0; m1r = nm1;

        float ps0 = 0.f, ps1 = 0.f;
#pragma unroll
        for (int nt = 0; nt < 8; nt++) {
            s[nt][0] = ex2f(s[nt][0] - nm0);
            s[nt][1] = ex2f(s[nt][1] - nm0);
            s[nt][2] = ex2f(s[nt][2] - nm1);
            s[nt][3] = ex2f(s[nt][3] - nm1);
            ps0 += s[nt][0] + s[nt][1];
            ps1 += s[nt][2] + s[nt][3];
        }
        ps0 += __shfl_xor_sync(0xffffffffu, ps0, 1);
        ps0 += __shfl_xor_sync(0xffffffffu, ps0, 2);
        ps1 += __shfl_xor_sync(0xffffffffu, ps1, 1);
        ps1 += __shfl_xor_sync(0xffffffffu, ps1, 2);
        l0 = l0*a0 + ps0;
        l1 = l1*a1 + ps1;

#pragma unroll
        for (int nt = 0; nt < 8; nt++) {
            o[nt][0] *= a0; o[nt][1] *= a0; o[nt][2] *= a1; o[nt][3] *= a1;
        }

        // pack P into A-fragments (register-only, FA2 layout identity)
        unsigned pa[4][4];
#pragma unroll
        for (int c = 0; c < 4; c++) {
            const int e = 2*c;
            pa[c][0] = packbf(s[e][0],   s[e][1]);
            pa[c][1] = packbf(s[e][2],   s[e][3]);
            pa[c][2] = packbf(s[e+1][0], s[e+1][1]);
            pa[c][3] = packbf(s[e+1][2], s[e+1][3]);
        }

        // O += P @ V
#pragma unroll
        for (int c = 0; c < 4; c++) {
#pragma unroll
            for (int nt = 0; nt < 8; nt++) {
                unsigned b[2];
                b[0] = Vs[(nt*8+g)*36 + c*8 + qq];
                b[1] = Vs[(nt*8+g)*36 + c*8 + qq + 4];
                mma_bf16(o[nt], pa[c], b);
            }
        }
    }

    // epilogue: normalize, write merged heads [b][s][D] fp32
    const float inv0 = 1.f / l0, inv1 = 1.f / l1;
    const int b = bh >> 4, h = bh & 15;
    const int r0 = q0 + wid*16 + g, r1 = r0 + 8;
#pragma unroll
    for (int nt = 0; nt < 8; nt++) {
        const int col = h*HD_ + nt*8 + qq*2;
        float2 v0 = {o[nt][0]*inv0, o[nt][1]*inv0};
        float2 v1 = {o[nt][2]*inv1, o[nt][3]*inv1};
        *(float2*)&Y[(size_t)(b*S_ + r0)*D_ + col] = v0;
        *(float2*)&Y[(size_t)(b*S_ + r1)*D_ + col] = v1;
    }
}

// ---------------------------------------------------------------------------
extern "C" void kernel_launch(void* const* d_in, const int* in_sizes, int n_in,
                              void* d_out, int out_size) {
    (void)in_sizes; (void)n_in; (void)out_size;
    const float* q  = (const float*)d_in[0];
    const float* k  = (const float*)d_in[1];
    const float* v  = (const float*)d_in[2];
    const float* Wq = (const float*)d_in[3];
    const float* bq = (const float*)d_in[4];
    const float* Wk = (const float*)d_in[5];
    const float* bk = (const float*)d_in[6];
    const float* Wv = (const float*)d_in[7];
    const float* bv = (const float*)d_in[8];
    const float* Wo = (const float*)d_in[9];
    const float* bo = (const float*)d_in[10];
    float* out = (float*)d_out;

    void *gq, *gk, *gv, *gy;
    cudaGetSymbolAddress(&gq, g_qb);
    cudaGetSymbolAddress(&gk, g_kb);
    cudaGetSymbolAddress(&gv, g_vb);
    cudaGetSymbolAddress(&gy, g_y);

    dim3 thr(256);
    // Q, K projections: [8192,1024] -> bf16 headsplit
    proj_tc<1><<<dim3(1024/128, M_/128), thr>>>(q, Wq, bq, gq, QSCALE);
    proj_tc<1><<<dim3(1024/128, M_/128), thr>>>(k, Wk, bk, gk, 1.0f);
    // V projection, transposed output: compute V^T = Wv @ v^T  (X:=Wv, W:=v)
    proj_tc<2><<<dim3(M_/128, 1024/128), thr>>>(Wv, v, bv, gv, 1.0f);

    attn_tc<<<dim3(S_/64, B_*H_), dim3(128)>>>(
        (const __nv_bfloat16*)gq, (const __nv_bfloat16*)gk,
        (const __nv_bfloat16*)gv, (float*)gy);

    // output projection: fp32
    proj_tc<0><<<dim3(1024/128, M_/128), thr>>>((const float*)gy, Wo, bo, out, 1.0f);
}

// round 4
// speedup vs baseline: 9.8158x; 1.3510x over previous
#include <cuda_runtime.h>
#include <cuda_bf16.h>
#include <stdint.h>

#define B_  4
#define S_  2048
#define D_  1024
#define H_  16
#define HD_ 64
#define M_  (B_*S_)   // 8192

// log2(e) * (1/sqrt(64)) folded into Q projection epilogue
#define QSCALE 0.18033688011112042f

// Scratch (static device globals; no allocations allowed)
__device__ __nv_bfloat16 g_qb[B_*S_*D_];   // [bh][s][hd]
__device__ __nv_bfloat16 g_kb[B_*S_*D_];   // [bh][s][hd]
__device__ __nv_bfloat16 g_vb[B_*S_*D_];   // [bh][hd][s]  (transposed)
__device__ float g_y  [B_*S_*D_];          // attention out, tf32-rounded
__device__ float g_qc [B_*S_*D_];          // tf32-rounded inputs
__device__ float g_kc [B_*S_*D_];
__device__ float g_vc [B_*S_*D_];
__device__ float g_Wqc[D_*D_];
__device__ float g_Wkc[D_*D_];
__device__ float g_Wvc[D_*D_];
__device__ float g_Woc[D_*D_];

// ---------------------------------------------------------------------------
// helpers
// ---------------------------------------------------------------------------
__device__ __forceinline__ uint32_t smem_u32(const void* p) {
    uint32_t a;
    asm("{ .reg .u64 t; cvta.to.shared.u64 t, %1; cvt.u32.u64 %0, t; }"
        : "=r"(a) : "l"(p));
    return a;
}
__device__ __forceinline__ unsigned f2tf(float x) {
    unsigned r; asm("cvt.rna.tf32.f32 %0, %1;" : "=r"(r) : "f"(x)); return r;
}
__device__ __forceinline__ float ex2f(float x) {
    float r; asm("ex2.approx.f32 %0, %1;" : "=f"(r) : "f"(x)); return r;
}
__device__ __forceinline__ unsigned packbf(float lo, float hi) {
    __nv_bfloat162 h = __floats2bfloat162_rn(lo, hi);
    return *reinterpret_cast<unsigned*>(&h);
}
__device__ __forceinline__ void mma_tf32(float* c, const unsigned* a, const unsigned* b) {
    asm volatile("mma.sync.aligned.m16n8k8.row.col.f32.tf32.tf32.f32 "
        "{%0,%1,%2,%3},{%4,%5,%6,%7},{%8,%9},{%0,%1,%2,%3};"
        : "+f"(c[0]), "+f"(c[1]), "+f"(c[2]), "+f"(c[3])
        : "r"(a[0]), "r"(a[1]), "r"(a[2]), "r"(a[3]), "r"(b[0]), "r"(b[1]));
}
__device__ __forceinline__ void mma_bf16(float* c, const unsigned* a, const unsigned* b) {
    asm volatile("mma.sync.aligned.m16n8k16.row.col.f32.bf16.bf16.f32 "
        "{%0,%1,%2,%3},{%4,%5,%6,%7},{%8,%9},{%0,%1,%2,%3};"
        : "+f"(c[0]), "+f"(c[1]), "+f"(c[2]), "+f"(c[3])
        : "r"(a[0]), "r"(a[1]), "r"(a[2]), "r"(a[3]), "r"(b[0]), "r"(b[1]));
}
__device__ __forceinline__ void ldm4(unsigned* r, uint32_t addr) {
    asm volatile("ldmatrix.sync.aligned.m8n8.x4.shared.b16 {%0,%1,%2,%3}, [%4];"
        : "=r"(r[0]), "=r"(r[1]), "=r"(r[2]), "=r"(r[3]) : "r"(addr));
}
__device__ __forceinline__ void cpa16(uint32_t dst, const void* src) {
    asm volatile("cp.async.cg.shared.global [%0], [%1], 16;" :: "r"(dst), "l"(src));
}
__device__ __forceinline__ void cpa_commit() {
    asm volatile("cp.async.commit_group;" ::: "memory");
}
__device__ __forceinline__ void cpa_wait0() {
    asm volatile("cp.async.wait_group 0;" ::: "memory");
}

// ---------------------------------------------------------------------------
// convert: round fp32 -> tf32-format fp32 (once, removes per-block redundancy)
// ---------------------------------------------------------------------------
__global__ void cvt_tf32_kernel(const float4* __restrict__ in,
                                float4* __restrict__ out, int n4) {
    int i = blockIdx.x * blockDim.x + threadIdx.x;
    if (i < n4) {
        float4 v = in[i];
        v.x = __uint_as_float(f2tf(v.x));
        v.y = __uint_as_float(f2tf(v.y));
        v.z = __uint_as_float(f2tf(v.z));
        v.w = __uint_as_float(f2tf(v.w));
        out[i] = v;
    }
}

// ---------------------------------------------------------------------------
// tf32 projection GEMM with cp.async pipeline, pre-converted operands.
// out = relu(X @ W^T + bias) [* scale]
// X:[Mrows,1024], W:[Nrows,1024], both tf32-rounded fp32 row-major.
// Block tile 128(M) x 256(N), 256 threads = 8 warps of 64x64. K staged 32/stage.
// MODE 0: fp32 out [M,1024]            (bias on col)
// MODE 1: bf16 headsplit [B,H,S,HD]    (bias on col, * scale)
// MODE 2: bf16 transposed [B,H,HD,S]   (rows = features, bias on ROW)
// ---------------------------------------------------------------------------
#define PJ_A_BYTES (128*36*4)              // 18432 per stage
#define PJ_B_BYTES (256*36*4)              // 36864 per stage
#define PJ_SMEM    (2*(PJ_A_BYTES + PJ_B_BYTES))   // 110592

template<int MODE>
__global__ __launch_bounds__(256, 1)
void proj_tc(const float* __restrict__ X, const float* __restrict__ W,
             const float* __restrict__ bias, void* __restrict__ Yv, float scale)
{
    extern __shared__ char sm[];
    const uint32_t sb = smem_u32(sm);
    const int tid  = threadIdx.x;
    const int lane = tid & 31, wid = tid >> 5;
    const int g    = lane >> 2, qq = lane & 3;
    const int wm   = (wid & 1) * 64;      // 2 warp-rows
    const int wn   = (wid >> 1) * 64;     // 4 warp-cols
    const int m0   = blockIdx.y * 128, n0 = blockIdx.x * 256;

    auto issue = [&](int s, int buf) {
        const int k0 = s * 32;
#pragma unroll
        for (int i = 0; i < 4; i++) {
            const int c = i * 256 + tid;
            const int r = c >> 3, co = (c & 7) * 16;
            cpa16(sb + buf * PJ_A_BYTES + r * 144 + co,
                  (const char*)(X + (size_t)(m0 + r) * 1024 + k0) + co);
        }
#pragma unroll
        for (int i = 0; i < 8; i++) {
            const int c = i * 256 + tid;
            const int r = c >> 3, co = (c & 7) * 16;
            cpa16(sb + 2 * PJ_A_BYTES + buf * PJ_B_BYTES + r * 144 + co,
                  (const char*)(W + (size_t)(n0 + r) * 1024 + k0) + co);
        }
    };

    float acc[4][8][4];
#pragma unroll
    for (int mt = 0; mt < 4; mt++)
#pragma unroll
        for (int nt = 0; nt < 8; nt++)
#pragma unroll
            for (int j = 0; j < 4; j++) acc[mt][nt][j] = 0.f;

    issue(0, 0); cpa_commit();

    for (int s = 0; s < 32; s++) {
        cpa_wait0();
        __syncthreads();
        if (s < 31) { issue(s + 1, (s + 1) & 1); cpa_commit(); }

        const unsigned* As = (const unsigned*)(sm + (s & 1) * PJ_A_BYTES);
        const unsigned* Bs = (const unsigned*)(sm + 2 * PJ_A_BYTES + (s & 1) * PJ_B_BYTES);

#pragma unroll
        for (int ks = 0; ks < 4; ks++) {
            const int kb = ks * 8;
            unsigned a[4][4];
#pragma unroll
            for (int mt = 0; mt < 4; mt++) {
                const int r = wm + mt * 16 + g;
                a[mt][0] = As[r * 36 + kb + qq];
                a[mt][1] = As[(r + 8) * 36 + kb + qq];
                a[mt][2] = As[r * 36 + kb + qq + 4];
                a[mt][3] = As[(r + 8) * 36 + kb + qq + 4];
            }
#pragma unroll
            for (int nt = 0; nt < 8; nt++) {
                const int r = wn + nt * 8 + g;
                unsigned b[2];
                b[0] = Bs[r * 36 + kb + qq];
                b[1] = Bs[r * 36 + kb + qq + 4];
#pragma unroll
                for (int mt = 0; mt < 4; mt++) mma_tf32(acc[mt][nt], a[mt], b);
            }
        }
        __syncthreads();
    }

    // epilogue
#pragma unroll
    for (int mt = 0; mt < 4; mt++) {
        const int r0 = m0 + wm + mt * 16 + g;
        const int r1 = r0 + 8;
#pragma unroll
        for (int nt = 0; nt < 8; nt++) {
            const int c0 = n0 + wn + nt * 8 + qq * 2;
            float v00, v01, v10, v11;
            if (MODE == 2) {
                const float bb0 = bias[r0], bb1 = bias[r1];
                v00 = fmaxf(acc[mt][nt][0] + bb0, 0.f);
                v01 = fmaxf(acc[mt][nt][1] + bb0, 0.f);
                v10 = fmaxf(acc[mt][nt][2] + bb1, 0.f);
                v11 = fmaxf(acc[mt][nt][3] + bb1, 0.f);
            } else {
                const float bb0 = bias[c0], bb1 = bias[c0 + 1];
                v00 = fmaxf(acc[mt][nt][0] + bb0, 0.f) * scale;
                v01 = fmaxf(acc[mt][nt][1] + bb1, 0.f) * scale;
                v10 = fmaxf(acc[mt][nt][2] + bb0, 0.f) * scale;
                v11 = fmaxf(acc[mt][nt][3] + bb1, 0.f) * scale;
            }
            if (MODE == 0) {
                float* Y = (float*)Yv;
                float2 p0 = {v00, v01}, p1 = {v10, v11};
                *(float2*)&Y[(size_t)r0 * 1024 + c0] = p0;
                *(float2*)&Y[(size_t)r1 * 1024 + c0] = p1;
            } else if (MODE == 1) {
                __nv_bfloat16* Y = (__nv_bfloat16*)Yv;
                const int h = c0 >> 6, hd = c0 & 63;
                {
                    const int b = r0 >> 11, ss = r0 & 2047;
                    __nv_bfloat162 hh = __floats2bfloat162_rn(v00, v01);
                    *(__nv_bfloat162*)&Y[(((size_t)(b*H_ + h))*S_ + ss)*HD_ + hd] = hh;
                }
                {
                    const int b = r1 >> 11, ss = r1 & 2047;
                    __nv_bfloat162 hh = __floats2bfloat162_rn(v10, v11);
                    *(__nv_bfloat162*)&Y[(((size_t)(b*H_ + h))*S_ + ss)*HD_ + hd] = hh;
                }
            } else {
                __nv_bfloat16* Y = (__nv_bfloat16*)Yv;
                const int bcol = c0 >> 11, ss = c0 & 2047;
                {
                    const int h = r0 >> 6, hd = r0 & 63;
                    __nv_bfloat162 hh = __floats2bfloat162_rn(v00, v01);
                    *(__nv_bfloat162*)&Y[(((size_t)(bcol*H_ + h))*HD_ + hd)*S_ + ss] = hh;
                }
                {
                    const int h = r1 >> 6, hd = r1 & 63;
                    __nv_bfloat162 hh = __floats2bfloat162_rn(v10, v11);
                    *(__nv_bfloat162*)&Y[(((size_t)(bcol*H_ + h))*HD_ + hd)*S_ + ss] = hh;
                }
            }
        }
    }
}

// ---------------------------------------------------------------------------
// bf16 flash attention, ldmatrix + 32 q-rows/warp, cp.async KV double buffer.
// Q,K: [bh][s][hd] bf16.  V: [bh][hd][s] bf16.  Y: [b][s][D] fp32 (tf32-rounded).
// Block: 128 threads = 4 warps, each warp 32 q rows -> 128 q rows per block.
// ---------------------------------------------------------------------------
#define AT_Q_BYTES  (128*36*4)   // 18432
#define AT_KV_BYTES (64*36*4)    // 9216 per buffer
#define AT_SMEM     (AT_Q_BYTES + 4*AT_KV_BYTES)   // 55296

__global__ __launch_bounds__(128, 2)
void attn_tc(const __nv_bfloat16* __restrict__ Q,
             const __nv_bfloat16* __restrict__ K,
             const __nv_bfloat16* __restrict__ V,
             float* __restrict__ Y)
{
    extern __shared__ char sm[];
    uint32_t* Qs = (uint32_t*)sm;
    const uint32_t qsb = smem_u32(sm);
    const uint32_t ksb = qsb + AT_Q_BYTES;
    const uint32_t vsb = ksb + 2 * AT_KV_BYTES;

    const int tid  = threadIdx.x;
    const int lane = tid & 31, wq = tid >> 5;
    const int g    = lane >> 2, qq = lane & 3;
    const int l15  = lane & 15, lh = (lane >> 4) * 4;   // ldmatrix addressing
    const int bh   = blockIdx.y;
    const int q0   = blockIdx.x * 128;
    const size_t base = (size_t)bh * S_ * HD_;

    auto issue_kv = [&](int kt, int buf) {
#pragma unroll
        for (int i = 0; i < 4; i++) {
            const int c = i * 128 + tid;
            const int r = c >> 3, co = (c & 7) * 16;
            cpa16(ksb + buf * AT_KV_BYTES + r * 144 + co,
                  (const char*)(K + base + (size_t)(kt * 64 + r) * HD_) + co);
            cpa16(vsb + buf * AT_KV_BYTES + r * 144 + co,
                  (const char*)(V + base + (size_t)r * S_ + kt * 64) + co);
        }
    };

    issue_kv(0, 0); cpa_commit();

    // stage Q: one row per thread, 64 bf16 = 8 uint4
    {
        const uint4* src = (const uint4*)(Q + base + (size_t)(q0 + tid) * HD_);
#pragma unroll
        for (int j = 0; j < 8; j++) *(uint4*)&Qs[tid * 36 + j * 4] = src[j];
    }

    unsigned qa[2][4][4];
    float o[2][8][4];
    float mrow[2][2], lrow[2][2];
#pragma unroll
    for (int mt = 0; mt < 2; mt++) {
        mrow[mt][0] = -1e30f; mrow[mt][1] = -1e30f;
        lrow[mt][0] = 0.f;    lrow[mt][1] = 0.f;
#pragma unroll
        for (int nt = 0; nt < 8; nt++)
#pragma unroll
            for (int j = 0; j < 4; j++) o[mt][nt][j] = 0.f;
    }

    for (int kt = 0; kt < S_ / 64; kt++) {
        cpa_wait0();
        __syncthreads();
        if (kt == 0) {
            // load Q fragments once (valid after first barrier)
#pragma unroll
            for (int mt = 0; mt < 2; mt++)
#pragma unroll
                for (int c = 0; c < 4; c++)
                    ldm4(qa[mt][c],
                         qsb + ((wq * 32 + mt * 16 + l15) * 36 + c * 8 + lh) * 4);
        }
        if (kt + 1 < S_ / 64) { issue_kv(kt + 1, (kt + 1) & 1); cpa_commit(); }

        const uint32_t kb_ = ksb + (kt & 1) * AT_KV_BYTES;
        const uint32_t vb_ = vsb + (kt & 1) * AT_KV_BYTES;

        // S = Q @ K^T (log2-domain)
        float s[2][8][4];
#pragma unroll
        for (int mt = 0; mt < 2; mt++)
#pragma unroll
            for (int nt = 0; nt < 8; nt++)
#pragma unroll
                for (int j = 0; j < 4; j++) s[mt][nt][j] = 0.f;

#pragma unroll
        for (int c = 0; c < 4; c++) {
            unsigned kf[4][4];
#pragma unroll
            for (int np = 0; np < 4; np++)
                ldm4(kf[np], kb_ + ((np * 16 + l15) * 36 + c * 8 + lh) * 4);
#pragma unroll
            for (int np = 0; np < 4; np++) {
                unsigned b0[2] = {kf[np][0], kf[np][2]};
                unsigned b1[2] = {kf[np][1], kf[np][3]};
#pragma unroll
                for (int mt = 0; mt < 2; mt++) {
                    mma_bf16(s[mt][2 * np],     qa[mt][c], b0);
                    mma_bf16(s[mt][2 * np + 1], qa[mt][c], b1);
                }
            }
        }

        // online softmax (base-2) per mt
        unsigned pa[2][4][4];
#pragma unroll
        for (int mt = 0; mt < 2; mt++) {
            float mx0 = s[mt][0][0], mx1 = s[mt][0][2];
#pragma unroll
            for (int nt = 0; nt < 8; nt++) {
                mx0 = fmaxf(mx0, fmaxf(s[mt][nt][0], s[mt][nt][1]));
                mx1 = fmaxf(mx1, fmaxf(s[mt][nt][2], s[mt][nt][3]));
            }
            mx0 = fmaxf(mx0, __shfl_xor_sync(0xffffffffu, mx0, 1));
            mx0 = fmaxf(mx0, __shfl_xor_sync(0xffffffffu, mx0, 2));
            mx1 = fmaxf(mx1, __shfl_xor_sync(0xffffffffu, mx1, 1));
            mx1 = fmaxf(mx1, __shfl_xor_sync(0xffffffffu, mx1, 2));

            const float nm0 = fmaxf(mrow[mt][0], mx0);
            const float nm1 = fmaxf(mrow[mt][1], mx1);
            const float a0 = ex2f(mrow[mt][0] - nm0);
            const float a1 = ex2f(mrow[mt][1] - nm1);
            mrow[mt][0] = nm0; mrow[mt][1] = nm1;

            float ps0 = 0.f, ps1 = 0.f;
#pragma unroll
            for (int nt = 0; nt < 8; nt++) {
                s[mt][nt][0] = ex2f(s[mt][nt][0] - nm0);
                s[mt][nt][1] = ex2f(s[mt][nt][1] - nm0);
                s[mt][nt][2] = ex2f(s[mt][nt][2] - nm1);
                s[mt][nt][3] = ex2f(s[mt][nt][3] - nm1);
                ps0 += s[mt][nt][0] + s[mt][nt][1];
                ps1 += s[mt][nt][2] + s[mt][nt][3];
            }
            ps0 += __shfl_xor_sync(0xffffffffu, ps0, 1);
            ps0 += __shfl_xor_sync(0xffffffffu, ps0, 2);
            ps1 += __shfl_xor_sync(0xffffffffu, ps1, 1);
            ps1 += __shfl_xor_sync(0xffffffffu, ps1, 2);
            lrow[mt][0] = lrow[mt][0] * a0 + ps0;
            lrow[mt][1] = lrow[mt][1] * a1 + ps1;

#pragma unroll
            for (int nt = 0; nt < 8; nt++) {
                o[mt][nt][0] *= a0; o[mt][nt][1] *= a0;
                o[mt][nt][2] *= a1; o[mt][nt][3] *= a1;
            }
            // pack P into A-fragments (C-layout == A-layout identity)
#pragma unroll
            for (int c = 0; c < 4; c++) {
                pa[mt][c][0] = packbf(s[mt][2*c][0],   s[mt][2*c][1]);
                pa[mt][c][1] = packbf(s[mt][2*c][2],   s[mt][2*c][3]);
                pa[mt][c][2] = packbf(s[mt][2*c+1][0], s[mt][2*c+1][1]);
                pa[mt][c][3] = packbf(s[mt][2*c+1][2], s[mt][2*c+1][3]);
            }
        }

        // O += P @ V   (V stored [hd][s] -> B col-major fragments directly)
#pragma unroll
        for (int c = 0; c < 4; c++) {
            unsigned vf[4][4];
#pragma unroll
            for (int np = 0; np < 4; np++)
                ldm4(vf[np], vb_ + ((np * 16 + l15) * 36 + c * 8 + lh) * 4);
#pragma unroll
            for (int np = 0; np < 4; np++) {
                unsigned b0[2] = {vf[np][0], vf[np][2]};
                unsigned b1[2] = {vf[np][1], vf[np][3]};
#pragma unroll
                for (int mt = 0; mt < 2; mt++) {
                    mma_bf16(o[mt][2 * np],     pa[mt][c], b0);
                    mma_bf16(o[mt][2 * np + 1], pa[mt][c], b1);
                }
            }
        }
    }

    // epilogue: normalize, write merged heads, tf32-rounded (feeds O-proj)
    const int b = bh >> 4, h = bh & 15;
#pragma unroll
    for (int mt = 0; mt < 2; mt++) {
        const float inv0 = 1.f / lrow[mt][0], inv1 = 1.f / lrow[mt][1];
        const int r0 = q0 + wq * 32 + mt * 16 + g, r1 = r0 + 8;
#pragma unroll
        for (int nt = 0; nt < 8; nt++) {
            const int col = h * HD_ + nt * 8 + qq * 2;
            float2 v0, v1;
            v0.x = __uint_as_float(f2tf(o[mt][nt][0] * inv0));
            v0.y = __uint_as_float(f2tf(o[mt][nt][1] * inv0));
            v1.x = __uint_as_float(f2tf(o[mt][nt][2] * inv1));
            v1.y = __uint_as_float(f2tf(o[mt][nt][3] * inv1));
            *(float2*)&Y[(size_t)(b * S_ + r0) * D_ + col] = v0;
            *(float2*)&Y[(size_t)(b * S_ + r1) * D_ + col] = v1;
        }
    }
}

// ---------------------------------------------------------------------------
extern "C" void kernel_launch(void* const* d_in, const int* in_sizes, int n_in,
                              void* d_out, int out_size) {
    (void)in_sizes; (void)n_in; (void)out_size;
    const float* q  = (const float*)d_in[0];
    const float* k  = (const float*)d_in[1];
    const float* v  = (const float*)d_in[2];
    const float* Wq = (const float*)d_in[3];
    const float* bq = (const float*)d_in[4];
    const float* Wk = (const float*)d_in[5];
    const float* bk = (const float*)d_in[6];
    const float* Wv = (const float*)d_in[7];
    const float* bv = (const float*)d_in[8];
    const float* Wo = (const float*)d_in[9];
    const float* bo = (const float*)d_in[10];
    float* out = (float*)d_out;

    void *gqb, *gkb, *gvb, *gy;
    void *gqc, *gkc, *gvc, *gwq, *gwk, *gwv, *gwo;
    cudaGetSymbolAddress(&gqb, g_qb);
    cudaGetSymbolAddress(&gkb, g_kb);
    cudaGetSymbolAddress(&gvb, g_vb);
    cudaGetSymbolAddress(&gy,  g_y);
    cudaGetSymbolAddress(&gqc, g_qc);
    cudaGetSymbolAddress(&gkc, g_kc);
    cudaGetSymbolAddress(&gvc, g_vc);
    cudaGetSymbolAddress(&gwq, g_Wqc);
    cudaGetSymbolAddress(&gwk, g_Wkc);
    cudaGetSymbolAddress(&gwv, g_Wvc);
    cudaGetSymbolAddress(&gwo, g_Woc);

    cudaFuncSetAttribute(proj_tc<0>, cudaFuncAttributeMaxDynamicSharedMemorySize, PJ_SMEM);
    cudaFuncSetAttribute(proj_tc<1>, cudaFuncAttributeMaxDynamicSharedMemorySize, PJ_SMEM);
    cudaFuncSetAttribute(proj_tc<2>, cudaFuncAttributeMaxDynamicSharedMemorySize, PJ_SMEM);
    cudaFuncSetAttribute(attn_tc, cudaFuncAttributeMaxDynamicSharedMemorySize, AT_SMEM);

    // tf32 pre-conversion (removes redundant per-block cvt; enables cp.async)
    const int nX4 = (B_*S_*D_) / 4, nW4 = (D_*D_) / 4;
    cvt_tf32_kernel<<<(nX4 + 255)/256, 256>>>((const float4*)q, (float4*)gqc, nX4);
    cvt_tf32_kernel<<<(nX4 + 255)/256, 256>>>((const float4*)k, (float4*)gkc, nX4);
    cvt_tf32_kernel<<<(nX4 + 255)/256, 256>>>((const float4*)v, (float4*)gvc, nX4);
    cvt_tf32_kernel<<<(nW4 + 255)/256, 256>>>((const float4*)Wq, (float4*)gwq, nW4);
    cvt_tf32_kernel<<<(nW4 + 255)/256, 256>>>((const float4*)Wk, (float4*)gwk, nW4);
    cvt_tf32_kernel<<<(nW4 + 255)/256, 256>>>((const float4*)Wv, (float4*)gwv, nW4);
    cvt_tf32_kernel<<<(nW4 + 255)/256, 256>>>((const float4*)Wo, (float4*)gwo, nW4);

    dim3 thr(256);
    // Q,K projections: bf16 headsplit [B,H,S,HD]
    proj_tc<1><<<dim3(4, 64), thr, PJ_SMEM>>>((const float*)gqc, (const float*)gwq, bq, gqb, QSCALE);
    proj_tc<1><<<dim3(4, 64), thr, PJ_SMEM>>>((const float*)gkc, (const float*)gwk, bk, gkb, 1.0f);
    // V projection transposed: V^T = Wv @ v^T  (X:=Wv [1024 rows], W:=v [8192 rows])
    proj_tc<2><<<dim3(32, 8), thr, PJ_SMEM>>>((const float*)gwv, (const float*)gvc, bv, gvb, 1.0f);

    attn_tc<<<dim3(S_/128, B_*H_), dim3(128), AT_SMEM>>>(
        (const __nv_bfloat16*)gqb, (const __nv_bfloat16*)gkb,
        (const __nv_bfloat16*)gvb, (float*)gy);

    // output projection: fp32 out
    proj_tc<0><<<dim3(4, 64), thr, PJ_SMEM>>>((const float*)gy, (const float*)gwo, bo, out, 1.0f);
}

// round 5
// speedup vs baseline: 9.8701x; 1.0055x over previous
#include <cuda_runtime.h>
#include <cuda_bf16.h>
#include <stdint.h>

#define B_  4
#define S_  2048
#define D_  1024
#define H_  16
#define HD_ 64
#define M_  (B_*S_)   // 8192

// log2(e) * (1/sqrt(64)) folded into Q projection epilogue
#define QSCALE 0.18033688011112042f

// Scratch (static device globals; no allocations allowed)
__device__ __nv_bfloat16 g_qb[B_*S_*D_];   // [bh][s][hd]
__device__ __nv_bfloat16 g_kb[B_*S_*D_];   // [bh][s][hd]
__device__ __nv_bfloat16 g_vb[B_*S_*D_];   // [bh][hd][s]  (transposed)
__device__ float g_y  [B_*S_*D_];          // attention out, tf32-rounded
__device__ float g_qc [B_*S_*D_];          // tf32-rounded inputs
__device__ float g_kc [B_*S_*D_];
__device__ float g_vc [B_*S_*D_];
__device__ float g_Wqc[D_*D_];
__device__ float g_Wkc[D_*D_];
__device__ float g_Wvc[D_*D_];
__device__ float g_Woc[D_*D_];

// ---------------------------------------------------------------------------
// helpers
// ---------------------------------------------------------------------------
__device__ __forceinline__ uint32_t smem_u32(const void* p) {
    uint32_t a;
    asm("{ .reg .u64 t; cvta.to.shared.u64 t, %1; cvt.u32.u64 %0, t; }"
        : "=r"(a) : "l"(p));
    return a;
}
__device__ __forceinline__ unsigned f2tf(float x) {
    unsigned r; asm("cvt.rna.tf32.f32 %0, %1;" : "=r"(r) : "f"(x)); return r;
}
__device__ __forceinline__ float ex2f(float x) {
    float r; asm("ex2.approx.f32 %0, %1;" : "=f"(r) : "f"(x)); return r;
}
__device__ __forceinline__ unsigned packbf(float lo, float hi) {
    __nv_bfloat162 h = __floats2bfloat162_rn(lo, hi);
    return *reinterpret_cast<unsigned*>(&h);
}
__device__ __forceinline__ void mma_tf32(float* c, const unsigned* a, const unsigned* b) {
    asm volatile("mma.sync.aligned.m16n8k8.row.col.f32.tf32.tf32.f32 "
        "{%0,%1,%2,%3},{%4,%5,%6,%7},{%8,%9},{%0,%1,%2,%3};"
        : "+f"(c[0]), "+f"(c[1]), "+f"(c[2]), "+f"(c[3])
        : "r"(a[0]), "r"(a[1]), "r"(a[2]), "r"(a[3]), "r"(b[0]), "r"(b[1]));
}
__device__ __forceinline__ void mma_bf16(float* c, const unsigned* a, const unsigned* b) {
    asm volatile("mma.sync.aligned.m16n8k16.row.col.f32.bf16.bf16.f32 "
        "{%0,%1,%2,%3},{%4,%5,%6,%7},{%8,%9},{%0,%1,%2,%3};"
        : "+f"(c[0]), "+f"(c[1]), "+f"(c[2]), "+f"(c[3])
        : "r"(a[0]), "r"(a[1]), "r"(a[2]), "r"(a[3]), "r"(b[0]), "r"(b[1]));
}
__device__ __forceinline__ void ldm4(unsigned* r, uint32_t addr) {
    asm volatile("ldmatrix.sync.aligned.m8n8.x4.shared.b16 {%0,%1,%2,%3}, [%4];"
        : "=r"(r[0]), "=r"(r[1]), "=r"(r[2]), "=r"(r[3]) : "r"(addr));
}
__device__ __forceinline__ void cpa16(uint32_t dst, const void* src) {
    asm volatile("cp.async.cg.shared.global [%0], [%1], 16;" :: "r"(dst), "l"(src));
}
__device__ __forceinline__ void cpa_commit() {
    asm volatile("cp.async.commit_group;" ::: "memory");
}
__device__ __forceinline__ void cpa_wait0() {
    asm volatile("cp.async.wait_group 0;" ::: "memory");
}
__device__ __forceinline__ void cpa_wait1() {
    asm volatile("cp.async.wait_group 1;" ::: "memory");
}

// ---------------------------------------------------------------------------
// fused convert: round all 7 fp32 tensors to tf32-format fp32 in ONE launch.
// (also aligns ncu -s 5 onto the final projection kernel)
// ---------------------------------------------------------------------------
#define NI4 ((B_*S_*D_)/4)    // 2097152 float4 per input tensor
#define NW4 ((D_*D_)/4)       // 262144 float4 per weight
#define NCVT4 (3*NI4 + 4*NW4) // 7339008

__global__ void cvt_all_kernel(
    const float4* __restrict__ q,  const float4* __restrict__ k,
    const float4* __restrict__ v,  const float4* __restrict__ w0,
    const float4* __restrict__ w1, const float4* __restrict__ w2,
    const float4* __restrict__ w3,
    float4* __restrict__ dq,  float4* __restrict__ dk,
    float4* __restrict__ dv,  float4* __restrict__ dw0,
    float4* __restrict__ dw1, float4* __restrict__ dw2,
    float4* __restrict__ dw3)
{
    int i = blockIdx.x * blockDim.x + threadIdx.x;
    if (i >= NCVT4) return;
    const float4* src; float4* dst; int off;
    if (i < 3*NI4) {
        int t = i / NI4; off = i - t*NI4;
        src = (t == 0) ? q : (t == 1) ? k : v;
        dst = (t == 0) ? dq : (t == 1) ? dk : dv;
    } else {
        int j = i - 3*NI4; int t = j / NW4; off = j - t*NW4;
        src = (t == 0) ? w0 : (t == 1) ? w1 : (t == 2) ? w2 : w3;
        dst = (t == 0) ? dw0 : (t == 1) ? dw1 : (t == 2) ? dw2 : dw3;
    }
    float4 x = src[off];
    x.x = __uint_as_float(f2tf(x.x));
    x.y = __uint_as_float(f2tf(x.y));
    x.z = __uint_as_float(f2tf(x.z));
    x.w = __uint_as_float(f2tf(x.w));
    dst[off] = x;
}

// ---------------------------------------------------------------------------
// tf32 projection GEMM, 3-stage cp.async ring, pre-converted operands.
// out = relu(X @ W^T + bias) [* scale]
// Block tile 128(M) x 256(N), 256 threads = 8 warps of 64x64. K=32/stage.
// MODE 0: fp32 out [M,1024]; MODE 1: bf16 headsplit [B,H,S,HD] (*scale);
// MODE 2: bf16 transposed [B,H,HD,S] (bias on ROW).
// ---------------------------------------------------------------------------
#define PJ_A_BYTES (128*36*4)                  // 18432
#define PJ_B_BYTES (256*36*4)                  // 36864
#define PJ_STG     (PJ_A_BYTES + PJ_B_BYTES)   // 55296 per stage
#define PJ_SMEM    (3*PJ_STG)                  // 165888

template<int MODE>
__global__ __launch_bounds__(256, 1)
void proj_tc(const float* __restrict__ X, const float* __restrict__ W,
             const float* __restrict__ bias, void* __restrict__ Yv, float scale)
{
    extern __shared__ char sm[];
    const uint32_t sb = smem_u32(sm);
    const int tid  = threadIdx.x;
    const int lane = tid & 31, wid = tid >> 5;
    const int g    = lane >> 2, qq = lane & 3;
    const int wm   = (wid & 1) * 64;
    const int wn   = (wid >> 1) * 64;
    const int m0   = blockIdx.y * 128, n0 = blockIdx.x * 256;

    auto issue = [&](int s) {
        const int k0 = s * 32;
        const uint32_t base = sb + (uint32_t)(s % 3) * PJ_STG;
#pragma unroll
        for (int i = 0; i < 4; i++) {
            const int c = i * 256 + tid;
            const int r = c >> 3, co = (c & 7) * 16;
            cpa16(base + r * 144 + co,
                  (const char*)(X + (size_t)(m0 + r) * 1024 + k0) + co);
        }
#pragma unroll
        for (int i = 0; i < 8; i++) {
            const int c = i * 256 + tid;
            const int r = c >> 3, co = (c & 7) * 16;
            cpa16(base + PJ_A_BYTES + r * 144 + co,
                  (const char*)(W + (size_t)(n0 + r) * 1024 + k0) + co);
        }
    };

    float acc[4][8][4];
#pragma unroll
    for (int mt = 0; mt < 4; mt++)
#pragma unroll
        for (int nt = 0; nt < 8; nt++)
#pragma unroll
            for (int j = 0; j < 4; j++) acc[mt][nt][j] = 0.f;

    issue(0); cpa_commit();
    issue(1); cpa_commit();

    for (int s = 0; s < 32; s++) {
        if (s < 31) cpa_wait1(); else cpa_wait0();
        __syncthreads();
        if (s + 2 < 32) { issue(s + 2); cpa_commit(); }

        const unsigned* As = (const unsigned*)(sm + (s % 3) * PJ_STG);
        const unsigned* Bs = As + PJ_A_BYTES / 4;

#pragma unroll
        for (int ks = 0; ks < 4; ks++) {
            const int kb = ks * 8;
            unsigned a[4][4];
#pragma unroll
            for (int mt = 0; mt < 4; mt++) {
                const int r = wm + mt * 16 + g;
                a[mt][0] = As[r * 36 + kb + qq];
                a[mt][1] = As[(r + 8) * 36 + kb + qq];
                a[mt][2] = As[r * 36 + kb + qq + 4];
                a[mt][3] = As[(r + 8) * 36 + kb + qq + 4];
            }
#pragma unroll
            for (int nt = 0; nt < 8; nt++) {
                const int r = wn + nt * 8 + g;
                unsigned b[2];
                b[0] = Bs[r * 36 + kb + qq];
                b[1] = Bs[r * 36 + kb + qq + 4];
#pragma unroll
                for (int mt = 0; mt < 4; mt++) mma_tf32(acc[mt][nt], a[mt], b);
            }
        }
    }

    // epilogue
#pragma unroll
    for (int mt = 0; mt < 4; mt++) {
        const int r0 = m0 + wm + mt * 16 + g;
        const int r1 = r0 + 8;
#pragma unroll
        for (int nt = 0; nt < 8; nt++) {
            const int c0 = n0 + wn + nt * 8 + qq * 2;
            float v00, v01, v10, v11;
            if (MODE == 2) {
                const float bb0 = bias[r0], bb1 = bias[r1];
                v00 = fmaxf(acc[mt][nt][0] + bb0, 0.f);
                v01 = fmaxf(acc[mt][nt][1] + bb0, 0.f);
                v10 = fmaxf(acc[mt][nt][2] + bb1, 0.f);
                v11 = fmaxf(acc[mt][nt][3] + bb1, 0.f);
            } else {
                const float bb0 = bias[c0], bb1 = bias[c0 + 1];
                v00 = fmaxf(acc[mt][nt][0] + bb0, 0.f) * scale;
                v01 = fmaxf(acc[mt][nt][1] + bb1, 0.f) * scale;
                v10 = fmaxf(acc[mt][nt][2] + bb0, 0.f) * scale;
                v11 = fmaxf(acc[mt][nt][3] + bb1, 0.f) * scale;
            }
            if (MODE == 0) {
                float* Y = (float*)Yv;
                float2 p0 = {v00, v01}, p1 = {v10, v11};
                *(float2*)&Y[(size_t)r0 * 1024 + c0] = p0;
                *(float2*)&Y[(size_t)r1 * 1024 + c0] = p1;
            } else if (MODE == 1) {
                __nv_bfloat16* Y = (__nv_bfloat16*)Yv;
                const int h = c0 >> 6, hd = c0 & 63;
                {
                    const int b = r0 >> 11, ss = r0 & 2047;
                    __nv_bfloat162 hh = __floats2bfloat162_rn(v00, v01);
                    *(__nv_bfloat162*)&Y[(((size_t)(b*H_ + h))*S_ + ss)*HD_ + hd] = hh;
                }
                {
                    const int b = r1 >> 11, ss = r1 & 2047;
                    __nv_bfloat162 hh = __floats2bfloat162_rn(v10, v11);
                    *(__nv_bfloat162*)&Y[(((size_t)(b*H_ + h))*S_ + ss)*HD_ + hd] = hh;
                }
            } else {
                __nv_bfloat16* Y = (__nv_bfloat16*)Yv;
                const int bcol = c0 >> 11, ss = c0 & 2047;
                {
                    const int h = r0 >> 6, hd = r0 & 63;
                    __nv_bfloat162 hh = __floats2bfloat162_rn(v00, v01);
                    *(__nv_bfloat162*)&Y[(((size_t)(bcol*H_ + h))*HD_ + hd)*S_ + ss] = hh;
                }
                {
                    const int h = r1 >> 6, hd = r1 & 63;
                    __nv_bfloat162 hh = __floats2bfloat162_rn(v10, v11);
                    *(__nv_bfloat162*)&Y[(((size_t)(bcol*H_ + h))*HD_ + hd)*S_ + ss] = hh;
                }
            }
        }
    }
}

// ---------------------------------------------------------------------------
// bf16 flash attention (unchanged from R4 — known good).
// Q,K: [bh][s][hd] bf16.  V: [bh][hd][s] bf16.  Y: [b][s][D] fp32 (tf32-rounded).
// ---------------------------------------------------------------------------
#define AT_Q_BYTES  (128*36*4)   // 18432
#define AT_KV_BYTES (64*36*4)    // 9216 per buffer
#define AT_SMEM     (AT_Q_BYTES + 4*AT_KV_BYTES)   // 55296

__global__ __launch_bounds__(128, 2)
void attn_tc(const __nv_bfloat16* __restrict__ Q,
             const __nv_bfloat16* __restrict__ K,
             const __nv_bfloat16* __restrict__ V,
             float* __restrict__ Y)
{
    extern __shared__ char sm[];
    uint32_t* Qs = (uint32_t*)sm;
    const uint32_t qsb = smem_u32(sm);
    const uint32_t ksb = qsb + AT_Q_BYTES;
    const uint32_t vsb = ksb + 2 * AT_KV_BYTES;

    const int tid  = threadIdx.x;
    const int lane = tid & 31, wq = tid >> 5;
    const int g    = lane >> 2, qq = lane & 3;
    const int l15  = lane & 15, lh = (lane >> 4) * 4;
    const int bh   = blockIdx.y;
    const int q0   = blockIdx.x * 128;
    const size_t base = (size_t)bh * S_ * HD_;

    auto issue_kv = [&](int kt, int buf) {
#pragma unroll
        for (int i = 0; i < 4; i++) {
            const int c = i * 128 + tid;
            const int r = c >> 3, co = (c & 7) * 16;
            cpa16(ksb + buf * AT_KV_BYTES + r * 144 + co,
                  (const char*)(K + base + (size_t)(kt * 64 + r) * HD_) + co);
            cpa16(vsb + buf * AT_KV_BYTES + r * 144 + co,
                  (const char*)(V + base + (size_t)r * S_ + kt * 64) + co);
        }
    };

    issue_kv(0, 0); cpa_commit();

    {
        const uint4* src = (const uint4*)(Q + base + (size_t)(q0 + tid) * HD_);
#pragma unroll
        for (int j = 0; j < 8; j++) *(uint4*)&Qs[tid * 36 + j * 4] = src[j];
    }

    unsigned qa[2][4][4];
    float o[2][8][4];
    float mrow[2][2], lrow[2][2];
#pragma unroll
    for (int mt = 0; mt < 2; mt++) {
        mrow[mt][0] = -1e30f; mrow[mt][1] = -1e30f;
        lrow[mt][0] = 0.f;    lrow[mt][1] = 0.f;
#pragma unroll
        for (int nt = 0; nt < 8; nt++)
#pragma unroll
            for (int j = 0; j < 4; j++) o[mt][nt][j] = 0.f;
    }

    for (int kt = 0; kt < S_ / 64; kt++) {
        cpa_wait0();
        __syncthreads();
        if (kt == 0) {
#pragma unroll
            for (int mt = 0; mt < 2; mt++)
#pragma unroll
                for (int c = 0; c < 4; c++)
                    ldm4(qa[mt][c],
                         qsb + ((wq * 32 + mt * 16 + l15) * 36 + c * 8 + lh) * 4);
        }
        if (kt + 1 < S_ / 64) { issue_kv(kt + 1, (kt + 1) & 1); cpa_commit(); }

        const uint32_t kb_ = ksb + (kt & 1) * AT_KV_BYTES;
        const uint32_t vb_ = vsb + (kt & 1) * AT_KV_BYTES;

        float s[2][8][4];
#pragma unroll
        for (int mt = 0; mt < 2; mt++)
#pragma unroll
            for (int nt = 0; nt < 8; nt++)
#pragma unroll
                for (int j = 0; j < 4; j++) s[mt][nt][j] = 0.f;

#pragma unroll
        for (int c = 0; c < 4; c++) {
            unsigned kf[4][4];
#pragma unroll
            for (int np = 0; np < 4; np++)
                ldm4(kf[np], kb_ + ((np * 16 + l15) * 36 + c * 8 + lh) * 4);
#pragma unroll
            for (int np = 0; np < 4; np++) {
                unsigned b0[2] = {kf[np][0], kf[np][2]};
                unsigned b1[2] = {kf[np][1], kf[np][3]};
#pragma unroll
                for (int mt = 0; mt < 2; mt++) {
                    mma_bf16(s[mt][2 * np],     qa[mt][c], b0);
                    mma_bf16(s[mt][2 * np + 1], qa[mt][c], b1);
                }
            }
        }

        unsigned pa[2][4][4];
#pragma unroll
        for (int mt = 0; mt < 2; mt++) {
            float mx0 = s[mt][0][0], mx1 = s[mt][0][2];
#pragma unroll
            for (int nt = 0; nt < 8; nt++) {
                mx0 = fmaxf(mx0, fmaxf(s[mt][nt][0], s[mt][nt][1]));
                mx1 = fmaxf(mx1, fmaxf(s[mt][nt][2], s[mt][nt][3]));
            }
            mx0 = fmaxf(mx0, __shfl_xor_sync(0xffffffffu, mx0, 1));
            mx0 = fmaxf(mx0, __shfl_xor_sync(0xffffffffu, mx0, 2));
            mx1 = fmaxf(mx1, __shfl_xor_sync(0xffffffffu, mx1, 1));
            mx1 = fmaxf(mx1, __shfl_xor_sync(0xffffffffu, mx1, 2));

            const float nm0 = fmaxf(mrow[mt][0], mx0);
            const float nm1 = fmaxf(mrow[mt][1], mx1);
            const float a0 = ex2f(mrow[mt][0] - nm0);
            const float a1 = ex2f(mrow[mt][1] - nm1);
            mrow[mt][0] = nm0; mrow[mt][1] = nm1;

            float ps0 = 0.f, ps1 = 0.f;
#pragma unroll
            for (int nt = 0; nt < 8; nt++) {
                s[mt][nt][0] = ex2f(s[mt][nt][0] - nm0);
                s[mt][nt][1] = ex2f(s[mt][nt][1] - nm0);
                s[mt][nt][2] = ex2f(s[mt][nt][2] - nm1);
                s[mt][nt][3] = ex2f(s[mt][nt][3] - nm1);
                ps0 += s[mt][nt][0] + s[mt][nt][1];
                ps1 += s[mt][nt][2] + s[mt][nt][3];
            }
            ps0 += __shfl_xor_sync(0xffffffffu, ps0, 1);
            ps0 += __shfl_xor_sync(0xffffffffu, ps0, 2);
            ps1 += __shfl_xor_sync(0xffffffffu, ps1, 1);
            ps1 += __shfl_xor_sync(0xffffffffu, ps1, 2);
            lrow[mt][0] = lrow[mt][0] * a0 + ps0;
            lrow[mt][1] = lrow[mt][1] * a1 + ps1;

#pragma unroll
            for (int nt = 0; nt < 8; nt++) {
                o[mt][nt][0] *= a0; o[mt][nt][1] *= a0;
                o[mt][nt][2] *= a1; o[mt][nt][3] *= a1;
            }
#pragma unroll
            for (int c = 0; c < 4; c++) {
                pa[mt][c][0] = packbf(s[mt][2*c][0],   s[mt][2*c][1]);
                pa[mt][c][1] = packbf(s[mt][2*c][2],   s[mt][2*c][3]);
                pa[mt][c][2] = packbf(s[mt][2*c+1][0], s[mt][2*c+1][1]);
                pa[mt][c][3] = packbf(s[mt][2*c+1][2], s[mt][2*c+1][3]);
            }
        }

#pragma unroll
        for (int c = 0; c < 4; c++) {
            unsigned vf[4][4];
#pragma unroll
            for (int np = 0; np < 4; np++)
                ldm4(vf[np], vb_ + ((np * 16 + l15) * 36 + c * 8 + lh) * 4);
#pragma unroll
            for (int np = 0; np < 4; np++) {
                unsigned b0[2] = {vf[np][0], vf[np][2]};
                unsigned b1[2] = {vf[np][1], vf[np][3]};
#pragma unroll
                for (int mt = 0; mt < 2; mt++) {
                    mma_bf16(o[mt][2 * np],     pa[mt][c], b0);
                    mma_bf16(o[mt][2 * np + 1], pa[mt][c], b1);
                }
            }
        }
    }

    const int b = bh >> 4, h = bh & 15;
#pragma unroll
    for (int mt = 0; mt < 2; mt++) {
        const float inv0 = 1.f / lrow[mt][0], inv1 = 1.f / lrow[mt][1];
        const int r0 = q0 + wq * 32 + mt * 16 + g, r1 = r0 + 8;
#pragma unroll
        for (int nt = 0; nt < 8; nt++) {
            const int col = h * HD_ + nt * 8 + qq * 2;
            float2 v0, v1;
            v0.x = __uint_as_float(f2tf(o[mt][nt][0] * inv0));
            v0.y = __uint_as_float(f2tf(o[mt][nt][1] * inv0));
            v1.x = __uint_as_float(f2tf(o[mt][nt][2] * inv1));
            v1.y = __uint_as_float(f2tf(o[mt][nt][3] * inv1));
            *(float2*)&Y[(size_t)(b * S_ + r0) * D_ + col] = v0;
            *(float2*)&Y[(size_t)(b * S_ + r1) * D_ + col] = v1;
        }
    }
}

// ---------------------------------------------------------------------------
extern "C" void kernel_launch(void* const* d_in, const int* in_sizes, int n_in,
                              void* d_out, int out_size) {
    (void)in_sizes; (void)n_in; (void)out_size;
    const float* q  = (const float*)d_in[0];
    const float* k  = (const float*)d_in[1];
    const float* v  = (const float*)d_in[2];
    const float* Wq = (const float*)d_in[3];
    const float* bq = (const float*)d_in[4];
    const float* Wk = (const float*)d_in[5];
    const float* bk = (const float*)d_in[6];
    const float* Wv = (const float*)d_in[7];
    const float* bv = (const float*)d_in[8];
    const float* Wo = (const float*)d_in[9];
    const float* bo = (const float*)d_in[10];
    float* out = (float*)d_out;

    void *gqb, *gkb, *gvb, *gy;
    void *gqc, *gkc, *gvc, *gwq, *gwk, *gwv, *gwo;
    cudaGetSymbolAddress(&gqb, g_qb);
    cudaGetSymbolAddress(&gkb, g_kb);
    cudaGetSymbolAddress(&gvb, g_vb);
    cudaGetSymbolAddress(&gy,  g_y);
    cudaGetSymbolAddress(&gqc, g_qc);
    cudaGetSymbolAddress(&gkc, g_kc);
    cudaGetSymbolAddress(&gvc, g_vc);
    cudaGetSymbolAddress(&gwq, g_Wqc);
    cudaGetSymbolAddress(&gwk, g_Wkc);
    cudaGetSymbolAddress(&gwv, g_Wvc);
    cudaGetSymbolAddress(&gwo, g_Woc);

    cudaFuncSetAttribute(proj_tc<0>, cudaFuncAttributeMaxDynamicSharedMemorySize, PJ_SMEM);
    cudaFuncSetAttribute(proj_tc<1>, cudaFuncAttributeMaxDynamicSharedMemorySize, PJ_SMEM);
    cudaFuncSetAttribute(proj_tc<2>, cudaFuncAttributeMaxDynamicSharedMemorySize, PJ_SMEM);
    cudaFuncSetAttribute(attn_tc, cudaFuncAttributeMaxDynamicSharedMemorySize, AT_SMEM);

    // single fused tf32 pre-conversion launch
    cvt_all_kernel<<<(NCVT4 + 255)/256, 256>>>(
        (const float4*)q,  (const float4*)k,  (const float4*)v,
        (const float4*)Wq, (const float4*)Wk, (const float4*)Wv, (const float4*)Wo,
        (float4*)gqc, (float4*)gkc, (float4*)gvc,
        (float4*)gwq, (float4*)gwk, (float4*)gwv, (float4*)gwo);

    dim3 thr(256);
    // Q,K projections: bf16 headsplit [B,H,S,HD]
    proj_tc<1><<<dim3(4, 64), thr, PJ_SMEM>>>((const float*)gqc, (const float*)gwq, bq, gqb, QSCALE);
    proj_tc<1><<<dim3(4, 64), thr, PJ_SMEM>>>((const float*)gkc, (const float*)gwk, bk, gkb, 1.0f);
    // V projection transposed: V^T = Wv @ v^T  (X:=Wv [1024 rows], W:=v [8192 rows])
    proj_tc<2><<<dim3(32, 8), thr, PJ_SMEM>>>((const float*)gwv, (const float*)gvc, bv, gvb, 1.0f);

    attn_tc<<<dim3(S_/128, B_*H_), dim3(128), AT_SMEM>>>(
        (const __nv_bfloat16*)gqb, (const __nv_bfloat16*)gkb,
        (const __nv_bfloat16*)gvb, (float*)gy);

    // output projection: fp32 out  (ncu -s 5 profiles THIS launch)
    proj_tc<0><<<dim3(4, 64), thr, PJ_SMEM>>>((const float*)gy, (const float*)gwo, bo, out, 1.0f);
}

// round 6
// speedup vs baseline: 10.4434x; 1.0581x over previous
#include <cuda_runtime.h>
#include <cuda_bf16.h>
#include <stdint.h>

#define B_  4
#define S_  2048
#define D_  1024
#define H_  16
#define HD_ 64
#define M_  (B_*S_)   // 8192

// log2(e) * (1/sqrt(64)) folded into Q projection epilogue
#define QSCALE 0.18033688011112042f

// Scratch (static device globals; no allocations allowed)
__device__ __nv_bfloat16 g_qb[B_*S_*D_];   // [bh][s][hd]
__device__ __nv_bfloat16 g_kb[B_*S_*D_];   // [bh][s][hd]
__device__ __nv_bfloat16 g_vb[B_*S_*D_];   // [bh][hd][s]  (transposed)
__device__ float g_y  [B_*S_*D_];          // attention out, tf32-rounded
__device__ float g_qc [B_*S_*D_];          // tf32-rounded inputs
__device__ float g_kc [B_*S_*D_];
__device__ float g_vc [B_*S_*D_];
__device__ float g_Wqc[D_*D_];
__device__ float g_Wkc[D_*D_];
__device__ float g_Wvc[D_*D_];
__device__ float g_Woc[D_*D_];

// ---------------------------------------------------------------------------
// helpers
// ---------------------------------------------------------------------------
__device__ __forceinline__ uint32_t smem_u32(const void* p) {
    uint32_t a;
    asm("{ .reg .u64 t; cvta.to.shared.u64 t, %1; cvt.u32.u64 %0, t; }"
        : "=r"(a) : "l"(p));
    return a;
}
__device__ __forceinline__ unsigned f2tf(float x) {
    unsigned r; asm("cvt.rna.tf32.f32 %0, %1;" : "=r"(r) : "f"(x)); return r;
}
__device__ __forceinline__ float ex2f(float x) {
    float r; asm("ex2.approx.f32 %0, %1;" : "=f"(r) : "f"(x)); return r;
}
__device__ __forceinline__ unsigned packbf(float lo, float hi) {
    __nv_bfloat162 h = __floats2bfloat162_rn(lo, hi);
    return *reinterpret_cast<unsigned*>(&h);
}
__device__ __forceinline__ void mma_tf32(float* c, const unsigned* a, const unsigned* b) {
    asm volatile("mma.sync.aligned.m16n8k8.row.col.f32.tf32.tf32.f32 "
        "{%0,%1,%2,%3},{%4,%5,%6,%7},{%8,%9},{%0,%1,%2,%3};"
        : "+f"(c[0]), "+f"(c[1]), "+f"(c[2]), "+f"(c[3])
        : "r"(a[0]), "r"(a[1]), "r"(a[2]), "r"(a[3]), "r"(b[0]), "r"(b[1]));
}
__device__ __forceinline__ void mma_bf16(float* c, const unsigned* a, const unsigned* b) {
    asm volatile("mma.sync.aligned.m16n8k16.row.col.f32.bf16.bf16.f32 "
        "{%0,%1,%2,%3},{%4,%5,%6,%7},{%8,%9},{%0,%1,%2,%3};"
        : "+f"(c[0]), "+f"(c[1]), "+f"(c[2]), "+f"(c[3])
        : "r"(a[0]), "r"(a[1]), "r"(a[2]), "r"(a[3]), "r"(b[0]), "r"(b[1]));
}
__device__ __forceinline__ void ldm4(unsigned* r, uint32_t addr) {
    asm volatile("ldmatrix.sync.aligned.m8n8.x4.shared.b16 {%0,%1,%2,%3}, [%4];"
        : "=r"(r[0]), "=r"(r[1]), "=r"(r[2]), "=r"(r[3]) : "r"(addr));
}
__device__ __forceinline__ void cpa16(uint32_t dst, const void* src) {
    asm volatile("cp.async.cg.shared.global [%0], [%1], 16;" :: "r"(dst), "l"(src));
}
__device__ __forceinline__ void cpa_commit() {
    asm volatile("cp.async.commit_group;" ::: "memory");
}
__device__ __forceinline__ void cpa_wait0() {
    asm volatile("cp.async.wait_group 0;" ::: "memory");
}
__device__ __forceinline__ void cpa_wait1() {
    asm volatile("cp.async.wait_group 1;" ::: "memory");
}

// ---------------------------------------------------------------------------
// fused convert: all 7 fp32 tensors -> tf32-format fp32, one launch
// ---------------------------------------------------------------------------
#define NI4 ((B_*S_*D_)/4)
#define NW4 ((D_*D_)/4)
#define NCVT4 (3*NI4 + 4*NW4)

__global__ void cvt_all_kernel(
    const float4* __restrict__ q,  const float4* __restrict__ k,
    const float4* __restrict__ v,  const float4* __restrict__ w0,
    const float4* __restrict__ w1, const float4* __restrict__ w2,
    const float4* __restrict__ w3,
    float4* __restrict__ dq,  float4* __restrict__ dk,
    float4* __restrict__ dv,  float4* __restrict__ dw0,
    float4* __restrict__ dw1, float4* __restrict__ dw2,
    float4* __restrict__ dw3)
{
    int i = blockIdx.x * blockDim.x + threadIdx.x;
    if (i >= NCVT4) return;
    const float4* src; float4* dst; int off;
    if (i < 3*NI4) {
        int t = i / NI4; off = i - t*NI4;
        src = (t == 0) ? q : (t == 1) ? k : v;
        dst = (t == 0) ? dq : (t == 1) ? dk : dv;
    } else {
        int j = i - 3*NI4; int t = j / NW4; off = j - t*NW4;
        src = (t == 0) ? w0 : (t == 1) ? w1 : (t == 2) ? w2 : w3;
        dst = (t == 0) ? dw0 : (t == 1) ? dw1 : (t == 2) ? dw2 : dw3;
    }
    float4 x = src[off];
    x.x = __uint_as_float(f2tf(x.x));
    x.y = __uint_as_float(f2tf(x.y));
    x.z = __uint_as_float(f2tf(x.z));
    x.w = __uint_as_float(f2tf(x.w));
    dst[off] = x;
}

// ---------------------------------------------------------------------------
// tf32 projection GEMM, 128x128 tile, 256 thr, 3-stage ring, 2 blocks/SM.
// COMBINED=1: grid (8,64,3) -> z selects Q(mode1,QSCALE)/K(mode1)/V(mode2).
// COMBINED=0: grid (8,64)   -> single mode-0 GEMM (fp32 out).
// out = relu(X @ W^T + bias) [* scale]
// mode 1: bf16 headsplit [B,H,S,HD]; mode 2: bf16 transposed [B,H,HD,S]
//         (V: X:=Wv so m indexes features, n indexes tokens; bias on row)
// Warps: 8 = 4(M) x 2(N), each 32x64 -> acc[2][8][4] (64 regs).
// ---------------------------------------------------------------------------
#define P2_HALF  (128*36*4)          // 18432 (A or B per stage)
#define P2_STG   (2*P2_HALF)         // 36864
#define P2_SMEM  (3*P2_STG)          // 110592 -> 2 blocks/SM

template<int COMBINED>
__global__ __launch_bounds__(256, 2)
void proj128(const float* __restrict__ X0, const float* __restrict__ W0,
             const float* __restrict__ b0p, void* __restrict__ Y0,
             const float* __restrict__ X1, const float* __restrict__ W1,
             const float* __restrict__ b1p, void* __restrict__ Y1,
             const float* __restrict__ X2, const float* __restrict__ W2,
             const float* __restrict__ b2p, void* __restrict__ Y2)
{
    extern __shared__ char sm[];
    const uint32_t sb = smem_u32(sm);
    const int tid  = threadIdx.x;
    const int lane = tid & 31, wid = tid >> 5;
    const int g    = lane >> 2, qq = lane & 3;
    const int wm   = (wid & 3) * 32;     // 4 M-warps
    const int wn   = (wid >> 2) * 64;    // 2 N-warps

    const float* X; const float* W; const float* bias; void* Yv;
    int mode; float scale = 1.0f;
    int m0, n0;
    if (COMBINED) {
        const int z = blockIdx.z;
        if (z == 0)      { X = X0; W = W0; bias = b0p; Yv = Y0; mode = 1; scale = QSCALE; }
        else if (z == 1) { X = X1; W = W1; bias = b1p; Yv = Y1; mode = 1; }
        else             { X = X2; W = W2; bias = b2p; Yv = Y2; mode = 2; }
        if (z == 2) { m0 = blockIdx.x * 128; n0 = blockIdx.y * 128; }
        else        { m0 = blockIdx.y * 128; n0 = blockIdx.x * 128; }
    } else {
        X = X0; W = W0; bias = b0p; Yv = Y0; mode = 0;
        m0 = blockIdx.y * 128; n0 = blockIdx.x * 128;
    }

    auto issue = [&](int s) {
        const int k0 = s * 32;
        const uint32_t base = sb + (uint32_t)(s % 3) * P2_STG;
#pragma unroll
        for (int i = 0; i < 4; i++) {
            const int c = i * 256 + tid;          // 0..1023
            const int r = c >> 3, co = (c & 7) * 16;
            cpa16(base + r * 144 + co,
                  (const char*)(X + (size_t)(m0 + r) * 1024 + k0) + co);
        }
#pragma unroll
        for (int i = 0; i < 4; i++) {
            const int c = i * 256 + tid;
            const int r = c >> 3, co = (c & 7) * 16;
            cpa16(base + P2_HALF + r * 144 + co,
                  (const char*)(W + (size_t)(n0 + r) * 1024 + k0) + co);
        }
    };

    float acc[2][8][4];
#pragma unroll
    for (int mt = 0; mt < 2; mt++)
#pragma unroll
        for (int nt = 0; nt < 8; nt++)
#pragma unroll
            for (int j = 0; j < 4; j++) acc[mt][nt][j] = 0.f;

    issue(0); cpa_commit();
    issue(1); cpa_commit();

    for (int s = 0; s < 32; s++) {
        if (s < 31) cpa_wait1(); else cpa_wait0();
        __syncthreads();
        if (s + 2 < 32) { issue(s + 2); cpa_commit(); }

        const unsigned* As = (const unsigned*)(sm + (s % 3) * P2_STG);
        const unsigned* Bs = As + P2_HALF / 4;

#pragma unroll
        for (int ks = 0; ks < 4; ks++) {
            const int kb = ks * 8;
            unsigned a[2][4];
#pragma unroll
            for (int mt = 0; mt < 2; mt++) {
                const int r = wm + mt * 16 + g;
                a[mt][0] = As[r * 36 + kb + qq];
                a[mt][1] = As[(r + 8) * 36 + kb + qq];
                a[mt][2] = As[r * 36 + kb + qq + 4];
                a[mt][3] = As[(r + 8) * 36 + kb + qq + 4];
            }
#pragma unroll
            for (int nt = 0; nt < 8; nt++) {
                const int r = wn + nt * 8 + g;
                unsigned b[2];
                b[0] = Bs[r * 36 + kb + qq];
                b[1] = Bs[r * 36 + kb + qq + 4];
#pragma unroll
                for (int mt = 0; mt < 2; mt++) mma_tf32(acc[mt][nt], a[mt], b);
            }
        }
    }

    // epilogue
#pragma unroll
    for (int mt = 0; mt < 2; mt++) {
        const int r0 = m0 + wm + mt * 16 + g;
        const int r1 = r0 + 8;
#pragma unroll
        for (int nt = 0; nt < 8; nt++) {
            const int c0 = n0 + wn + nt * 8 + qq * 2;
            float v00, v01, v10, v11;
            if (COMBINED && mode == 2) {
                const float bb0 = bias[r0], bb1 = bias[r1];
                v00 = fmaxf(acc[mt][nt][0] + bb0, 0.f);
                v01 = fmaxf(acc[mt][nt][1] + bb0, 0.f);
                v10 = fmaxf(acc[mt][nt][2] + bb1, 0.f);
                v11 = fmaxf(acc[mt][nt][3] + bb1, 0.f);
            } else {
                const float bb0 = bias[c0], bb1 = bias[c0 + 1];
                v00 = fmaxf(acc[mt][nt][0] + bb0, 0.f) * scale;
                v01 = fmaxf(acc[mt][nt][1] + bb1, 0.f) * scale;
                v10 = fmaxf(acc[mt][nt][2] + bb0, 0.f) * scale;
                v11 = fmaxf(acc[mt][nt][3] + bb1, 0.f) * scale;
            }
            if (!COMBINED) {
                float* Y = (float*)Yv;
                float2 p0 = {v00, v01}, p1 = {v10, v11};
                *(float2*)&Y[(size_t)r0 * 1024 + c0] = p0;
                *(float2*)&Y[(size_t)r1 * 1024 + c0] = p1;
            } else if (mode == 1) {
                __nv_bfloat16* Y = (__nv_bfloat16*)Yv;
                const int h = c0 >> 6, hd = c0 & 63;
                {
                    const int b = r0 >> 11, ss = r0 & 2047;
                    __nv_bfloat162 hh = __floats2bfloat162_rn(v00, v01);
                    *(__nv_bfloat162*)&Y[(((size_t)(b*H_ + h))*S_ + ss)*HD_ + hd] = hh;
                }
                {
                    const int b = r1 >> 11, ss = r1 & 2047;
                    __nv_bfloat162 hh = __floats2bfloat162_rn(v10, v11);
                    *(__nv_bfloat162*)&Y[(((size_t)(b*H_ + h))*S_ + ss)*HD_ + hd] = hh;
                }
            } else {
                __nv_bfloat16* Y = (__nv_bfloat16*)Yv;
                const int bcol = c0 >> 11, ss = c0 & 2047;
                {
                    const int h = r0 >> 6, hd = r0 & 63;
                    __nv_bfloat162 hh = __floats2bfloat162_rn(v00, v01);
                    *(__nv_bfloat162*)&Y[(((size_t)(bcol*H_ + h))*HD_ + hd)*S_ + ss] = hh;
                }
                {
                    const int h = r1 >> 6, hd = r1 & 63;
                    __nv_bfloat162 hh = __floats2bfloat162_rn(v10, v11);
                    *(__nv_bfloat162*)&Y[(((size_t)(bcol*H_ + h))*HD_ + hd)*S_ + ss] = hh;
                }
            }
        }
    }
}

// ---------------------------------------------------------------------------
// bf16 flash attention (unchanged — known good).
// Q,K: [bh][s][hd] bf16.  V: [bh][hd][s] bf16.  Y: [b][s][D] fp32 (tf32-rounded).
// ---------------------------------------------------------------------------
#define AT_Q_BYTES  (128*36*4)
#define AT_KV_BYTES (64*36*4)
#define AT_SMEM     (AT_Q_BYTES + 4*AT_KV_BYTES)

__global__ __launch_bounds__(128, 2)
void attn_tc(const __nv_bfloat16* __restrict__ Q,
             const __nv_bfloat16* __restrict__ K,
             const __nv_bfloat16* __restrict__ V,
             float* __restrict__ Y)
{
    extern __shared__ char sm[];
    uint32_t* Qs = (uint32_t*)sm;
    const uint32_t qsb = smem_u32(sm);
    const uint32_t ksb = qsb + AT_Q_BYTES;
    const uint32_t vsb = ksb + 2 * AT_KV_BYTES;

    const int tid  = threadIdx.x;
    const int lane = tid & 31, wq = tid >> 5;
    const int g    = lane >> 2, qq = lane & 3;
    const int l15  = lane & 15, lh = (lane >> 4) * 4;
    const int bh   = blockIdx.y;
    const int q0   = blockIdx.x * 128;
    const size_t base = (size_t)bh * S_ * HD_;

    auto issue_kv = [&](int kt, int buf) {
#pragma unroll
        for (int i = 0; i < 4; i++) {
            const int c = i * 128 + tid;
            const int r = c >> 3, co = (c & 7) * 16;
            cpa16(ksb + buf * AT_KV_BYTES + r * 144 + co,
                  (const char*)(K + base + (size_t)(kt * 64 + r) * HD_) + co);
            cpa16(vsb + buf * AT_KV_BYTES + r * 144 + co,
                  (const char*)(V + base + (size_t)r * S_ + kt * 64) + co);
        }
    };

    issue_kv(0, 0); cpa_commit();

    {
        const uint4* src = (const uint4*)(Q + base + (size_t)(q0 + tid) * HD_);
#pragma unroll
        for (int j = 0; j < 8; j++) *(uint4*)&Qs[tid * 36 + j * 4] = src[j];
    }

    unsigned qa[2][4][4];
    float o[2][8][4];
    float mrow[2][2], lrow[2][2];
#pragma unroll
    for (int mt = 0; mt < 2; mt++) {
        mrow[mt][0] = -1e30f; mrow[mt][1] = -1e30f;
        lrow[mt][0] = 0.f;    lrow[mt][1] = 0.f;
#pragma unroll
        for (int nt = 0; nt < 8; nt++)
#pragma unroll
            for (int j = 0; j < 4; j++) o[mt][nt][j] = 0.f;
    }

    for (int kt = 0; kt < S_ / 64; kt++) {
        cpa_wait0();
        __syncthreads();
        if (kt == 0) {
#pragma unroll
            for (int mt = 0; mt < 2; mt++)
#pragma unroll
                for (int c = 0; c < 4; c++)
                    ldm4(qa[mt][c],
                         qsb + ((wq * 32 + mt * 16 + l15) * 36 + c * 8 + lh) * 4);
        }
        if (kt + 1 < S_ / 64) { issue_kv(kt + 1, (kt + 1) & 1); cpa_commit(); }

        const uint32_t kb_ = ksb + (kt & 1) * AT_KV_BYTES;
        const uint32_t vb_ = vsb + (kt & 1) * AT_KV_BYTES;

        float s[2][8][4];
#pragma unroll
        for (int mt = 0; mt < 2; mt++)
#pragma unroll
            for (int nt = 0; nt < 8; nt++)
#pragma unroll
                for (int j = 0; j < 4; j++) s[mt][nt][j] = 0.f;

#pragma unroll
        for (int c = 0; c < 4; c++) {
            unsigned kf[4][4];
#pragma unroll
            for (int np = 0; np < 4; np++)
                ldm4(kf[np], kb_ + ((np * 16 + l15) * 36 + c * 8 + lh) * 4);
#pragma unroll
            for (int np = 0; np < 4; np++) {
                unsigned b0[2] = {kf[np][0], kf[np][2]};
                unsigned b1[2] = {kf[np][1], kf[np][3]};
#pragma unroll
                for (int mt = 0; mt < 2; mt++) {
                    mma_bf16(s[mt][2 * np],     qa[mt][c], b0);
                    mma_bf16(s[mt][2 * np + 1], qa[mt][c], b1);
                }
            }
        }

        unsigned pa[2][4][4];
#pragma unroll
        for (int mt = 0; mt < 2; mt++) {
            float mx0 = s[mt][0][0], mx1 = s[mt][0][2];
#pragma unroll
            for (int nt = 0; nt < 8; nt++) {
                mx0 = fmaxf(mx0, fmaxf(s[mt][nt][0], s[mt][nt][1]));
                mx1 = fmaxf(mx1, fmaxf(s[mt][nt][2], s[mt][nt][3]));
            }
            mx0 = fmaxf(mx0, __shfl_xor_sync(0xffffffffu, mx0, 1));
            mx0 = fmaxf(mx0, __shfl_xor_sync(0xffffffffu, mx0, 2));
            mx1 = fmaxf(mx1, __shfl_xor_sync(0xffffffffu, mx1, 1));
            mx1 = fmaxf(mx1, __shfl_xor_sync(0xffffffffu, mx1, 2));

            const float nm0 = fmaxf(mrow[mt][0], mx0);
            const float nm1 = fmaxf(mrow[mt][1], mx1);
            const float a0 = ex2f(mrow[mt][0] - nm0);
            const float a1 = ex2f(mrow[mt][1] - nm1);
            mrow[mt][0] = nm0; mrow[mt][1] = nm1;

            float ps0 = 0.f, ps1 = 0.f;
#pragma unroll
            for (int nt = 0; nt < 8; nt++) {
                s[mt][nt][0] = ex2f(s[mt][nt][0] - nm0);
                s[mt][nt][1] = ex2f(s[mt][nt][1] - nm0);
                s[mt][nt][2] = ex2f(s[mt][nt][2] - nm1);
                s[mt][nt][3] = ex2f(s[mt][nt][3] - nm1);
                ps0 += s[mt][nt][0] + s[mt][nt][1];
                ps1 += s[mt][nt][2] + s[mt][nt][3];
            }
            ps0 += __shfl_xor_sync(0xffffffffu, ps0, 1);
            ps0 += __shfl_xor_sync(0xffffffffu, ps0, 2);
            ps1 += __shfl_xor_sync(0xffffffffu, ps1, 1);
            ps1 += __shfl_xor_sync(0xffffffffu, ps1, 2);
            lrow[mt][0] = lrow[mt][0] * a0 + ps0;
            lrow[mt][1] = lrow[mt][1] * a1 + ps1;

#pragma unroll
            for (int nt = 0; nt < 8; nt++) {
                o[mt][nt][0] *= a0; o[mt][nt][1] *= a0;
                o[mt][nt][2] *= a1; o[mt][nt][3] *= a1;
            }
#pragma unroll
            for (int c = 0; c < 4; c++) {
                pa[mt][c][0] = packbf(s[mt][2*c][0],   s[mt][2*c][1]);
                pa[mt][c][1] = packbf(s[mt][2*c][2],   s[mt][2*c][3]);
                pa[mt][c][2] = packbf(s[mt][2*c+1][0], s[mt][2*c+1][1]);
                pa[mt][c][3] = packbf(s[mt][2*c+1][2], s[mt][2*c+1][3]);
            }
        }

#pragma unroll
        for (int c = 0; c < 4; c++) {
            unsigned vf[4][4];
#pragma unroll
            for (int np = 0; np < 4; np++)
                ldm4(vf[np], vb_ + ((np * 16 + l15) * 36 + c * 8 + lh) * 4);
#pragma unroll
            for (int np = 0; np < 4; np++) {
                unsigned b0[2] = {vf[np][0], vf[np][2]};
                unsigned b1[2] = {vf[np][1], vf[np][3]};
#pragma unroll
                for (int mt = 0; mt < 2; mt++) {
                    mma_bf16(o[mt][2 * np],     pa[mt][c], b0);
                    mma_bf16(o[mt][2 * np + 1], pa[mt][c], b1);
                }
            }
        }
    }

    const int b = bh >> 4, h = bh & 15;
#pragma unroll
    for (int mt = 0; mt < 2; mt++) {
        const float inv0 = 1.f / lrow[mt][0], inv1 = 1.f / lrow[mt][1];
        const int r0 = q0 + wq * 32 + mt * 16 + g, r1 = r0 + 8;
#pragma unroll
        for (int nt = 0; nt < 8; nt++) {
            const int col = h * HD_ + nt * 8 + qq * 2;
            float2 v0, v1;
            v0.x = __uint_as_float(f2tf(o[mt][nt][0] * inv0));
            v0.y = __uint_as_float(f2tf(o[mt][nt][1] * inv0));
            v1.x = __uint_as_float(f2tf(o[mt][nt][2] * inv1));
            v1.y = __uint_as_float(f2tf(o[mt][nt][3] * inv1));
            *(float2*)&Y[(size_t)(b * S_ + r0) * D_ + col] = v0;
            *(float2*)&Y[(size_t)(b * S_ + r1) * D_ + col] = v1;
        }
    }
}

// ---------------------------------------------------------------------------
extern "C" void kernel_launch(void* const* d_in, const int* in_sizes, int n_in,
                              void* d_out, int out_size) {
    (void)in_sizes; (void)n_in; (void)out_size;
    const float* q  = (const float*)d_in[0];
    const float* k  = (const float*)d_in[1];
    const float* v  = (const float*)d_in[2];
    const float* Wq = (const float*)d_in[3];
    const float* bq = (const float*)d_in[4];
    const float* Wk = (const float*)d_in[5];
    const float* bk = (const float*)d_in[6];
    const float* Wv = (const float*)d_in[7];
    const float* bv = (const float*)d_in[8];
    const float* Wo = (const float*)d_in[9];
    const float* bo = (const float*)d_in[10];
    float* out = (float*)d_out;

    void *gqb, *gkb, *gvb, *gy;
    void *gqc, *gkc, *gvc, *gwq, *gwk, *gwv, *gwo;
    cudaGetSymbolAddress(&gqb, g_qb);
    cudaGetSymbolAddress(&gkb, g_kb);
    cudaGetSymbolAddress(&gvb, g_vb);
    cudaGetSymbolAddress(&gy,  g_y);
    cudaGetSymbolAddress(&gqc, g_qc);
    cudaGetSymbolAddress(&gkc, g_kc);
    cudaGetSymbolAddress(&gvc, g_vc);
    cudaGetSymbolAddress(&gwq, g_Wqc);
    cudaGetSymbolAddress(&gwk, g_Wkc);
    cudaGetSymbolAddress(&gwv, g_Wvc);
    cudaGetSymbolAddress(&gwo, g_Woc);

    cudaFuncSetAttribute(proj128<1>, cudaFuncAttributeMaxDynamicSharedMemorySize, P2_SMEM);
    cudaFuncSetAttribute(proj128<0>, cudaFuncAttributeMaxDynamicSharedMemorySize, P2_SMEM);
    cudaFuncSetAttribute(attn_tc, cudaFuncAttributeMaxDynamicSharedMemorySize, AT_SMEM);

    // single fused tf32 pre-conversion launch
    cvt_all_kernel<<<(NCVT4 + 255)/256, 256>>>(
        (const float4*)q,  (const float4*)k,  (const float4*)v,
        (const float4*)Wq, (const float4*)Wk, (const float4*)Wv, (const float4*)Wo,
        (float4*)gqc, (float4*)gkc, (float4*)gvc,
        (float4*)gwq, (float4*)gwk, (float4*)gwv, (float4*)gwo);

    // fused Q/K/V projections: z=0 Q (mode1, QSCALE), z=1 K (mode1), z=2 V (mode2)
    proj128<1><<<dim3(8, 64, 3), dim3(256), P2_SMEM>>>(
        (const float*)gqc, (const float*)gwq, bq, gqb,
        (const float*)gkc, (const float*)gwk, bk, gkb,
        (const float*)gwv, (const float*)gvc, bv, gvb);

    attn_tc<<<dim3(S_/128, B_*H_), dim3(128), AT_SMEM>>>(
        (const __nv_bfloat16*)gqb, (const __nv_bfloat16*)gkb,
        (const __nv_bfloat16*)gvb, (float*)gy);

    // output projection: fp32 out
    proj128<0><<<dim3(8, 64), dim3(256), P2_SMEM>>>(
        (const float*)gy, (const float*)gwo, bo, out,
        nullptr, nullptr, nullptr, nullptr,
        nullptr, nullptr, nullptr, nullptr);
}

// round 7
// speedup vs baseline: 13.9231x; 1.3332x over previous
#include <cuda_runtime.h>
#include <cuda_bf16.h>
#include <cuda_fp16.h>
#include <stdint.h>

#define B_  4
#define S_  2048
#define D_  1024
#define H_  16
#define HD_ 64
#define M_  (B_*S_)   // 8192

// log2(e) * (1/sqrt(64)) folded into Q projection epilogue
#define QSCALE 0.18033688011112042f

// Scratch (static device globals; no allocations allowed)
__device__ __nv_bfloat16 g_qb[B_*S_*D_];   // [bh][s][hd]
__device__ __nv_bfloat16 g_kb[B_*S_*D_];   // [bh][s][hd]
__device__ __nv_bfloat16 g_vb[B_*S_*D_];   // [bh][hd][s]  (transposed)
__device__ __half g_yh [B_*S_*D_];         // attention out, fp16
__device__ __half g_qh [B_*S_*D_];         // fp16 inputs
__device__ __half g_kh [B_*S_*D_];
__device__ __half g_vh [B_*S_*D_];
__device__ __half g_Wqh[D_*D_];
__device__ __half g_Wkh[D_*D_];
__device__ __half g_Wvh[D_*D_];
__device__ __half g_Woh[D_*D_];

// ---------------------------------------------------------------------------
// helpers
// ---------------------------------------------------------------------------
__device__ __forceinline__ uint32_t smem_u32(const void* p) {
    uint32_t a;
    asm("{ .reg .u64 t; cvta.to.shared.u64 t, %1; cvt.u32.u64 %0, t; }"
        : "=r"(a) : "l"(p));
    return a;
}
__device__ __forceinline__ float ex2f(float x) {
    float r; asm("ex2.approx.f32 %0, %1;" : "=f"(r) : "f"(x)); return r;
}
__device__ __forceinline__ unsigned packbf(float lo, float hi) {
    __nv_bfloat162 h = __floats2bfloat162_rn(lo, hi);
    return *reinterpret_cast<unsigned*>(&h);
}
__device__ __forceinline__ void mma_f16(float* c, const unsigned* a, const unsigned* b) {
    asm volatile("mma.sync.aligned.m16n8k16.row.col.f32.f16.f16.f32 "
        "{%0,%1,%2,%3},{%4,%5,%6,%7},{%8,%9},{%0,%1,%2,%3};"
        : "+f"(c[0]), "+f"(c[1]), "+f"(c[2]), "+f"(c[3])
        : "r"(a[0]), "r"(a[1]), "r"(a[2]), "r"(a[3]), "r"(b[0]), "r"(b[1]));
}
__device__ __forceinline__ void mma_bf16(float* c, const unsigned* a, const unsigned* b) {
    asm volatile("mma.sync.aligned.m16n8k16.row.col.f32.bf16.bf16.f32 "
        "{%0,%1,%2,%3},{%4,%5,%6,%7},{%8,%9},{%0,%1,%2,%3};"
        : "+f"(c[0]), "+f"(c[1]), "+f"(c[2]), "+f"(c[3])
        : "r"(a[0]), "r"(a[1]), "r"(a[2]), "r"(a[3]), "r"(b[0]), "r"(b[1]));
}
__device__ __forceinline__ void ldm4(unsigned* r, uint32_t addr) {
    asm volatile("ldmatrix.sync.aligned.m8n8.x4.shared.b16 {%0,%1,%2,%3}, [%4];"
        : "=r"(r[0]), "=r"(r[1]), "=r"(r[2]), "=r"(r[3]) : "r"(addr));
}
__device__ __forceinline__ void cpa16(uint32_t dst, const void* src) {
    asm volatile("cp.async.cg.shared.global [%0], [%1], 16;" :: "r"(dst), "l"(src));
}
__device__ __forceinline__ void cpa_commit() {
    asm volatile("cp.async.commit_group;" ::: "memory");
}
__device__ __forceinline__ void cpa_wait0() {
    asm volatile("cp.async.wait_group 0;" ::: "memory");
}
__device__ __forceinline__ void cpa_wait1() {
    asm volatile("cp.async.wait_group 1;" ::: "memory");
}

// ---------------------------------------------------------------------------
// fused convert: all 7 fp32 tensors -> fp16, one launch
// ---------------------------------------------------------------------------
#define NI4 ((B_*S_*D_)/4)
#define NW4 ((D_*D_)/4)
#define NCVT4 (3*NI4 + 4*NW4)

__global__ void cvt_all_kernel(
    const float4* __restrict__ q,  const float4* __restrict__ k,
    const float4* __restrict__ v,  const float4* __restrict__ w0,
    const float4* __restrict__ w1, const float4* __restrict__ w2,
    const float4* __restrict__ w3,
    __half* __restrict__ dq,  __half* __restrict__ dk,
    __half* __restrict__ dv,  __half* __restrict__ dw0,
    __half* __restrict__ dw1, __half* __restrict__ dw2,
    __half* __restrict__ dw3)
{
    int i = blockIdx.x * blockDim.x + threadIdx.x;
    if (i >= NCVT4) return;
    const float4* src; __half* dst; int off;
    if (i < 3*NI4) {
        int t = i / NI4; off = i - t*NI4;
        src = (t == 0) ? q : (t == 1) ? k : v;
        dst = (t == 0) ? dq : (t == 1) ? dk : dv;
    } else {
        int j = i - 3*NI4; int t = j / NW4; off = j - t*NW4;
        src = (t == 0) ? w0 : (t == 1) ? w1 : (t == 2) ? w2 : w3;
        dst = (t == 0) ? dw0 : (t == 1) ? dw1 : (t == 2) ? dw2 : dw3;
    }
    float4 x = src[off];
    __half2 h0 = __floats2half2_rn(x.x, x.y);
    __half2 h1 = __floats2half2_rn(x.z, x.w);
    uint2 o;
    o.x = *reinterpret_cast<unsigned*>(&h0);
    o.y = *reinterpret_cast<unsigned*>(&h1);
    reinterpret_cast<uint2*>(dst)[off] = o;
}

// ---------------------------------------------------------------------------
// fp16 projection GEMM (m16n8k16), 128x128 tile, 256 thr, 3-stage ring,
// 2 blocks/SM. out = relu(X @ W^T + bias) [* scale]
// COMBINED=1: grid (8,64,3): z=0 Q (mode1, QSCALE), z=1 K (mode1), z=2 V (mode2)
// COMBINED=0: grid (8,64): mode 0 (fp32 out).
// smem rows padded to 40 halfs (80B) -> all fragment LDS conflict-free.
// Warps: 8 = 4(M) x 2(N), each 32x64.
// ---------------------------------------------------------------------------
#define P3_HALF  (128*40*2)          // 10240 bytes (one operand, one stage)
#define P3_STG   (2*P3_HALF)         // 20480
#define P3_SMEM  (3*P3_STG)          // 61440 -> 2 blocks/SM easily

template<int COMBINED>
__global__ __launch_bounds__(256, 2)
void proj128(const __half* __restrict__ X0, const __half* __restrict__ W0,
             const float* __restrict__ b0p, void* __restrict__ Y0,
             const __half* __restrict__ X1, const __half* __restrict__ W1,
             const float* __restrict__ b1p, void* __restrict__ Y1,
             const __half* __restrict__ X2, const __half* __restrict__ W2,
             const float* __restrict__ b2p, void* __restrict__ Y2)
{
    extern __shared__ char sm[];
    const uint32_t sb = smem_u32(sm);
    const int tid  = threadIdx.x;
    const int lane = tid & 31, wid = tid >> 5;
    const int g    = lane >> 2, qq = lane & 3;
    const int wm   = (wid & 3) * 32;     // 4 M-warps
    const int wn   = (wid >> 2) * 64;    // 2 N-warps

    const __half* X; const __half* W; const float* bias; void* Yv;
    int mode; float scale = 1.0f;
    int m0, n0;
    if (COMBINED) {
        const int z = blockIdx.z;
        if (z == 0)      { X = X0; W = W0; bias = b0p; Yv = Y0; mode = 1; scale = QSCALE; }
        else if (z == 1) { X = X1; W = W1; bias = b1p; Yv = Y1; mode = 1; }
        else             { X = X2; W = W2; bias = b2p; Yv = Y2; mode = 2; }
        if (z == 2) { m0 = blockIdx.x * 128; n0 = blockIdx.y * 128; }
        else        { m0 = blockIdx.y * 128; n0 = blockIdx.x * 128; }
    } else {
        X = X0; W = W0; bias = b0p; Yv = Y0; mode = 0;
        m0 = blockIdx.y * 128; n0 = blockIdx.x * 128;
    }

    auto issue = [&](int s) {
        const int k0 = s * 32;   // in halfs
        const uint32_t base = sb + (uint32_t)(s % 3) * P3_STG;
#pragma unroll
        for (int i = 0; i < 2; i++) {
            const int c = i * 256 + tid;            // 0..511
            const int r = c >> 2, ch = (c & 3) * 16;
            cpa16(base + r * 80 + ch,
                  (const char*)(X + (size_t)(m0 + r) * 1024 + k0) + ch);
        }
#pragma unroll
        for (int i = 0; i < 2; i++) {
            const int c = i * 256 + tid;
            const int r = c >> 2, ch = (c & 3) * 16;
            cpa16(base + P3_HALF + r * 80 + ch,
                  (const char*)(W + (size_t)(n0 + r) * 1024 + k0) + ch);
        }
    };

    float acc[2][8][4];
#pragma unroll
    for (int mt = 0; mt < 2; mt++)
#pragma unroll
        for (int nt = 0; nt < 8; nt++)
#pragma unroll
            for (int j = 0; j < 4; j++) acc[mt][nt][j] = 0.f;

    issue(0); cpa_commit();
    issue(1); cpa_commit();

    for (int s = 0; s < 32; s++) {
        if (s < 31) cpa_wait1(); else cpa_wait0();
        __syncthreads();
        if (s + 2 < 32) { issue(s + 2); cpa_commit(); }

        const unsigned* As = (const unsigned*)(sm + (s % 3) * P3_STG);
        const unsigned* Bs = As + P3_HALF / 4;

#pragma unroll
        for (int kc = 0; kc < 2; kc++) {        // two K=16 chunks per stage
            const int kb = kc * 8;              // word offset
            unsigned a[2][4];
#pragma unroll
            for (int mt = 0; mt < 2; mt++) {
                const int r = wm + mt * 16 + g;
                a[mt][0] = As[r * 20 + kb + qq];
                a[mt][1] = As[(r + 8) * 20 + kb + qq];
                a[mt][2] = As[r * 20 + kb + qq + 4];
                a[mt][3] = As[(r + 8) * 20 + kb + qq + 4];
            }
#pragma unroll
            for (int nt = 0; nt < 8; nt++) {
                const int r = wn + nt * 8 + g;
                unsigned b[2];
                b[0] = Bs[r * 20 + kb + qq];
                b[1] = Bs[r * 20 + kb + qq + 4];
#pragma unroll
                for (int mt = 0; mt < 2; mt++) mma_f16(acc[mt][nt], a[mt], b);
            }
        }
    }

    // epilogue
#pragma unroll
    for (int mt = 0; mt < 2; mt++) {
        const int r0 = m0 + wm + mt * 16 + g;
        const int r1 = r0 + 8;
#pragma unroll
        for (int nt = 0; nt < 8; nt++) {
            const int c0 = n0 + wn + nt * 8 + qq * 2;
            float v00, v01, v10, v11;
            if (COMBINED && mode == 2) {
                const float bb0 = bias[r0], bb1 = bias[r1];
                v00 = fmaxf(acc[mt][nt][0] + bb0, 0.f);
                v01 = fmaxf(acc[mt][nt][1] + bb0, 0.f);
                v10 = fmaxf(acc[mt][nt][2] + bb1, 0.f);
                v11 = fmaxf(acc[mt][nt][3] + bb1, 0.f);
            } else {
                const float bb0 = bias[c0], bb1 = bias[c0 + 1];
                v00 = fmaxf(acc[mt][nt][0] + bb0, 0.f) * scale;
                v01 = fmaxf(acc[mt][nt][1] + bb1, 0.f) * scale;
                v10 = fmaxf(acc[mt][nt][2] + bb0, 0.f) * scale;
                v11 = fmaxf(acc[mt][nt][3] + bb1, 0.f) * scale;
            }
            if (!COMBINED) {
                float* Y = (float*)Yv;
                float2 p0 = {v00, v01}, p1 = {v10, v11};
                *(float2*)&Y[(size_t)r0 * 1024 + c0] = p0;
                *(float2*)&Y[(size_t)r1 * 1024 + c0] = p1;
            } else if (mode == 1) {
                __nv_bfloat16* Y = (__nv_bfloat16*)Yv;
                const int h = c0 >> 6, hd = c0 & 63;
                {
                    const int b = r0 >> 11, ss = r0 & 2047;
                    __nv_bfloat162 hh = __floats2bfloat162_rn(v00, v01);
                    *(__nv_bfloat162*)&Y[(((size_t)(b*H_ + h))*S_ + ss)*HD_ + hd] = hh;
                }
                {
                    const int b = r1 >> 11, ss = r1 & 2047;
                    __nv_bfloat162 hh = __floats2bfloat162_rn(v10, v11);
                    *(__nv_bfloat162*)&Y[(((size_t)(b*H_ + h))*S_ + ss)*HD_ + hd] = hh;
                }
            } else {
                __nv_bfloat16* Y = (__nv_bfloat16*)Yv;
                const int bcol = c0 >> 11, ss = c0 & 2047;
                {
                    const int h = r0 >> 6, hd = r0 & 63;
                    __nv_bfloat162 hh = __floats2bfloat162_rn(v00, v01);
                    *(__nv_bfloat162*)&Y[(((size_t)(bcol*H_ + h))*HD_ + hd)*S_ + ss] = hh;
                }
                {
                    const int h = r1 >> 6, hd = r1 & 63;
                    __nv_bfloat162 hh = __floats2bfloat162_rn(v10, v11);
                    *(__nv_bfloat162*)&Y[(((size_t)(bcol*H_ + h))*HD_ + hd)*S_ + ss] = hh;
                }
            }
        }
    }
}

// ---------------------------------------------------------------------------
// bf16 flash attention (mainloop unchanged — known good). Epilogue now fp16.
// Q,K: [bh][s][hd] bf16.  V: [bh][hd][s] bf16.  Y: [b][s][D] fp16.
// ---------------------------------------------------------------------------
#define AT_Q_BYTES  (128*36*4)
#define AT_KV_BYTES (64*36*4)
#define AT_SMEM     (AT_Q_BYTES + 4*AT_KV_BYTES)

__global__ __launch_bounds__(128, 2)
void attn_tc(const __nv_bfloat16* __restrict__ Q,
             const __nv_bfloat16* __restrict__ K,
             const __nv_bfloat16* __restrict__ V,
             __half* __restrict__ Y)
{
    extern __shared__ char sm[];
    uint32_t* Qs = (uint32_t*)sm;
    const uint32_t qsb = smem_u32(sm);
    const uint32_t ksb = qsb + AT_Q_BYTES;
    const uint32_t vsb = ksb + 2 * AT_KV_BYTES;

    const int tid  = threadIdx.x;
    const int lane = tid & 31, wq = tid >> 5;
    const int g    = lane >> 2, qq = lane & 3;
    const int l15  = lane & 15, lh = (lane >> 4) * 4;
    const int bh   = blockIdx.y;
    const int q0   = blockIdx.x * 128;
    const size_t base = (size_t)bh * S_ * HD_;

    auto issue_kv = [&](int kt, int buf) {
#pragma unroll
        for (int i = 0; i < 4; i++) {
            const int c = i * 128 + tid;
            const int r = c >> 3, co = (c & 7) * 16;
            cpa16(ksb + buf * AT_KV_BYTES + r * 144 + co,
                  (const char*)(K + base + (size_t)(kt * 64 + r) * HD_) + co);
            cpa16(vsb + buf * AT_KV_BYTES + r * 144 + co,
                  (const char*)(V + base + (size_t)r * S_ + kt * 64) + co);
        }
    };

    issue_kv(0, 0); cpa_commit();

    {
        const uint4* src = (const uint4*)(Q + base + (size_t)(q0 + tid) * HD_);
#pragma unroll
        for (int j = 0; j < 8; j++) *(uint4*)&Qs[tid * 36 + j * 4] = src[j];
    }

    unsigned qa[2][4][4];
    float o[2][8][4];
    float mrow[2][2], lrow[2][2];
#pragma unroll
    for (int mt = 0; mt < 2; mt++) {
        mrow[mt][0] = -1e30f; mrow[mt][1] = -1e30f;
        lrow[mt][0] = 0.f;    lrow[mt][1] = 0.f;
#pragma unroll
        for (int nt = 0; nt < 8; nt++)
#pragma unroll
            for (int j = 0; j < 4; j++) o[mt][nt][j] = 0.f;
    }

    for (int kt = 0; kt < S_ / 64; kt++) {
        cpa_wait0();
        __syncthreads();
        if (kt == 0) {
#pragma unroll
            for (int mt = 0; mt < 2; mt++)
#pragma unroll
                for (int c = 0; c < 4; c++)
                    ldm4(qa[mt][c],
                         qsb + ((wq * 32 + mt * 16 + l15) * 36 + c * 8 + lh) * 4);
        }
        if (kt + 1 < S_ / 64) { issue_kv(kt + 1, (kt + 1) & 1); cpa_commit(); }

        const uint32_t kb_ = ksb + (kt & 1) * AT_KV_BYTES;
        const uint32_t vb_ = vsb + (kt & 1) * AT_KV_BYTES;

        float s[2][8][4];
#pragma unroll
        for (int mt = 0; mt < 2; mt++)
#pragma unroll
            for (int nt = 0; nt < 8; nt++)
#pragma unroll
                for (int j = 0; j < 4; j++) s[mt][nt][j] = 0.f;

#pragma unroll
        for (int c = 0; c < 4; c++) {
            unsigned kf[4][4];
#pragma unroll
            for (int np = 0; np < 4; np++)
                ldm4(kf[np], kb_ + ((np * 16 + l15) * 36 + c * 8 + lh) * 4);
#pragma unroll
            for (int np = 0; np < 4; np++) {
                unsigned b0[2] = {kf[np][0], kf[np][2]};
                unsigned b1[2] = {kf[np][1], kf[np][3]};
#pragma unroll
                for (int mt = 0; mt < 2; mt++) {
                    mma_bf16(s[mt][2 * np],     qa[mt][c], b0);
                    mma_bf16(s[mt][2 * np + 1], qa[mt][c], b1);
                }
            }
        }

        unsigned pa[2][4][4];
#pragma unroll
        for (int mt = 0; mt < 2; mt++) {
            float mx0 = s[mt][0][0], mx1 = s[mt][0][2];
#pragma unroll
            for (int nt = 0; nt < 8; nt++) {
                mx0 = fmaxf(mx0, fmaxf(s[mt][nt][0], s[mt][nt][1]));
                mx1 = fmaxf(mx1, fmaxf(s[mt][nt][2], s[mt][nt][3]));
            }
            mx0 = fmaxf(mx0, __shfl_xor_sync(0xffffffffu, mx0, 1));
            mx0 = fmaxf(mx0, __shfl_xor_sync(0xffffffffu, mx0, 2));
            mx1 = fmaxf(mx1, __shfl_xor_sync(0xffffffffu, mx1, 1));
            mx1 = fmaxf(mx1, __shfl_xor_sync(0xffffffffu, mx1, 2));

            const float nm0 = fmaxf(mrow[mt][0], mx0);
            const float nm1 = fmaxf(mrow[mt][1], mx1);
            const float a0 = ex2f(mrow[mt][0] - nm0);
            const float a1 = ex2f(mrow[mt][1] - nm1);
            mrow[mt][0] = nm0; mrow[mt][1] = nm1;

            float ps0 = 0.f, ps1 = 0.f;
#pragma unroll
            for (int nt = 0; nt < 8; nt++) {
                s[mt][nt][0] = ex2f(s[mt][nt][0] - nm0);
                s[mt][nt][1] = ex2f(s[mt][nt][1] - nm0);
                s[mt][nt][2] = ex2f(s[mt][nt][2] - nm1);
                s[mt][nt][3] = ex2f(s[mt][nt][3] - nm1);
                ps0 += s[mt][nt][0] + s[mt][nt][1];
                ps1 += s[mt][nt][2] + s[mt][nt][3];
            }
            ps0 += __shfl_xor_sync(0xffffffffu, ps0, 1);
            ps0 += __shfl_xor_sync(0xffffffffu, ps0, 2);
            ps1 += __shfl_xor_sync(0xffffffffu, ps1, 1);
            ps1 += __shfl_xor_sync(0xffffffffu, ps1, 2);
            lrow[mt][0] = lrow[mt][0] * a0 + ps0;
            lrow[mt][1] = lrow[mt][1] * a1 + ps1;

#pragma unroll
            for (int nt = 0; nt < 8; nt++) {
                o[mt][nt][0] *= a0; o[mt][nt][1] *= a0;
                o[mt][nt][2] *= a1; o[mt][nt][3] *= a1;
            }
#pragma unroll
            for (int c = 0; c < 4; c++) {
                pa[mt][c][0] = packbf(s[mt][2*c][0],   s[mt][2*c][1]);
                pa[mt][c][1] = packbf(s[mt][2*c][2],   s[mt][2*c][3]);
                pa[mt][c][2] = packbf(s[mt][2*c+1][0], s[mt][2*c+1][1]);
                pa[mt][c][3] = packbf(s[mt][2*c+1][2], s[mt][2*c+1][3]);
            }
        }

#pragma unroll
        for (int c = 0; c < 4; c++) {
            unsigned vf[4][4];
#pragma unroll
            for (int np = 0; np < 4; np++)
                ldm4(vf[np], vb_ + ((np * 16 + l15) * 36 + c * 8 + lh) * 4);
#pragma unroll
            for (int np = 0; np < 4; np++) {
                unsigned b0[2] = {vf[np][0], vf[np][2]};
                unsigned b1[2] = {vf[np][1], vf[np][3]};
#pragma unroll
                for (int mt = 0; mt < 2; mt++) {
                    mma_bf16(o[mt][2 * np],     pa[mt][c], b0);
                    mma_bf16(o[mt][2 * np + 1], pa[mt][c], b1);
                }
            }
        }
    }

    // epilogue: normalize, write merged heads as fp16 (feeds O-projection)
    const int b = bh >> 4, h = bh & 15;
#pragma unroll
    for (int mt = 0; mt < 2; mt++) {
        const float inv0 = 1.f / lrow[mt][0], inv1 = 1.f / lrow[mt][1];
        const int r0 = q0 + wq * 32 + mt * 16 + g, r1 = r0 + 8;
#pragma unroll
        for (int nt = 0; nt < 8; nt++) {
            const int col = h * HD_ + nt * 8 + qq * 2;
            __half2 h0 = __floats2half2_rn(o[mt][nt][0] * inv0, o[mt][nt][1] * inv0);
            __half2 h1 = __floats2half2_rn(o[mt][nt][2] * inv1, o[mt][nt][3] * inv1);
            *(__half2*)&Y[(size_t)(b * S_ + r0) * D_ + col] = h0;
            *(__half2*)&Y[(size_t)(b * S_ + r1) * D_ + col] = h1;
        }
    }
}

// ---------------------------------------------------------------------------
extern "C" void kernel_launch(void* const* d_in, const int* in_sizes, int n_in,
                              void* d_out, int out_size) {
    (void)in_sizes; (void)n_in; (void)out_size;
    const float* q  = (const float*)d_in[0];
    const float* k  = (const float*)d_in[1];
    const float* v  = (const float*)d_in[2];
    const float* Wq = (const float*)d_in[3];
    const float* bq = (const float*)d_in[4];
    const float* Wk = (const float*)d_in[5];
    const float* bk = (const float*)d_in[6];
    const float* Wv = (const float*)d_in[7];
    const float* bv = (const float*)d_in[8];
    const float* Wo = (const float*)d_in[9];
    const float* bo = (const float*)d_in[10];
    float* out = (float*)d_out;

    void *gqb, *gkb, *gvb, *gyh;
    void *gqh, *gkh, *gvh, *gwq, *gwk, *gwv, *gwo;
    cudaGetSymbolAddress(&gqb, g_qb);
    cudaGetSymbolAddress(&gkb, g_kb);
    cudaGetSymbolAddress(&gvb, g_vb);
    cudaGetSymbolAddress(&gyh, g_yh);
    cudaGetSymbolAddress(&gqh, g_qh);
    cudaGetSymbolAddress(&gkh, g_kh);
    cudaGetSymbolAddress(&gvh, g_vh);
    cudaGetSymbolAddress(&gwq, g_Wqh);
    cudaGetSymbolAddress(&gwk, g_Wkh);
    cudaGetSymbolAddress(&gwv, g_Wvh);
    cudaGetSymbolAddress(&gwo, g_Woh);

    cudaFuncSetAttribute(proj128<1>, cudaFuncAttributeMaxDynamicSharedMemorySize, P3_SMEM);
    cudaFuncSetAttribute(proj128<0>, cudaFuncAttributeMaxDynamicSharedMemorySize, P3_SMEM);
    cudaFuncSetAttribute(attn_tc, cudaFuncAttributeMaxDynamicSharedMemorySize, AT_SMEM);

    // single fused fp16 pre-conversion launch
    cvt_all_kernel<<<(NCVT4 + 255)/256, 256>>>(
        (const float4*)q,  (const float4*)k,  (const float4*)v,
        (const float4*)Wq, (const float4*)Wk, (const float4*)Wv, (const float4*)Wo,
        (__half*)gqh, (__half*)gkh, (__half*)gvh,
        (__half*)gwq, (__half*)gwk, (__half*)gwv, (__half*)gwo);

    // fused Q/K/V projections
    proj128<1><<<dim3(8, 64, 3), dim3(256), P3_SMEM>>>(
        (const __half*)gqh, (const __half*)gwq, bq, gqb,
        (const __half*)gkh, (const __half*)gwk, bk, gkb,
        (const __half*)gwv, (const __half*)gvh, bv, gvb);

    attn_tc<<<dim3(S_/128, B_*H_), dim3(128), AT_SMEM>>>(
        (const __nv_bfloat16*)gqb, (const __nv_bfloat16*)gkb,
        (const __nv_bfloat16*)gvb, (__half*)gyh);

    // output projection: fp32 out
    proj128<0><<<dim3(8, 64), dim3(256), P3_SMEM>>>(
        (const __half*)gyh, (const __half*)gwo, bo, out,
        nullptr, nullptr, nullptr, nullptr,
        nullptr, nullptr, nullptr, nullptr);
}